// round 4
// baseline (speedup 1.0000x reference)
#include <cuda_runtime.h>
#include <math.h>

#define T_STEPS 200
#define B 256
#define XD 128
#define H 512
#define ZD 64
#define OD 256
#define G3 1536
#define NBLK 148
#define NTHR 512
#define UN 4
#define UT 128
#define NUNITS (NBLK * UN)   // 592

// per-unit smem tile geometry (floats)
#define AS_STRIDE 68
#define BS_STRIDE 68
#define AS_SZ (32 * AS_STRIDE)
#define BS_SZ (32 * BS_STRIDE)
#define BUF_SZ (AS_SZ + BS_SZ)               // 4352 floats
#define UNIT_SM (2 * BUF_SZ)                 // double buffered
#define SMEM_BYTES (UN * UNIT_SM * 4)        // ~139.3 KB

// ---------------- scratch ----------------
__device__ float g_phi[(size_t)T_STEPS * B * H];
__device__ float g_tmp[(size_t)T_STEPS * B * H];
__device__ float g_h [B * H];
__device__ float g_pr[B * H];
__device__ float g_e1[B * H];
__device__ float g_e2[B * H];
__device__ float g_pz[B * H];
__device__ float g_d1b[2][B * H];
__device__ float g_d2[B * H];
__device__ float g_gx[B * G3];
__device__ float g_gh[B * G3];

// ---------------- grid barrier ----------------
__device__ unsigned int g_bar = 0;
__device__ volatile unsigned int g_sense = 0;

__device__ __forceinline__ void gsync(unsigned* gen, bool last) {
    __syncthreads();
    if (threadIdx.x == 0) {
        __threadfence();
        unsigned g = *gen;
        if (atomicAdd(&g_bar, 1u) == (unsigned)(NBLK - 1)) {
            g_bar = 0u;
            __threadfence();
            g_sense = last ? 0u : (g + 1u);
        } else {
            while (g_sense == g) { __nanosleep(32); }
            __threadfence();
        }
    }
    __syncthreads();
    (*gen)++;
}

__device__ __forceinline__ void ubar(int id) {
    asm volatile("bar.sync %0, %1;" :: "r"(id), "r"(UT) : "memory");
}

// ---------------- helpers ----------------
__device__ __forceinline__ unsigned long long pk2(float x, float y) {
    unsigned long long r;
    asm("mov.b64 %0, {%1,%2};" : "=l"(r) : "f"(x), "f"(y));
    return r;
}
__device__ __forceinline__ float2 upk2(unsigned long long v) {
    float2 r;
    asm("mov.b64 {%0,%1}, %2;" : "=f"(r.x), "=f"(r.y) : "l"(v));
    return r;
}
__device__ __forceinline__ void ffma2(unsigned long long& d, unsigned long long a, unsigned long long b) {
    asm("fma.rn.f32x2 %0, %1, %2, %0;" : "+l"(d) : "l"(a), "l"(b));
}
__device__ __forceinline__ float actf(float v, int act) {
    if (act == 1) return fmaxf(v, 0.f);
    if (act == 2) return fmaxf(v, 0.f) + log1pf(expf(-fabsf(v)));
    return v;
}

// ---------------- 64x64 tile GEMM on a 128-thread unit ----------------
// per-thread: 8 rows x 4 cols. amode 0 plain / 1 concat / 2 z=eps*es+em.
// accum: C = act(C_old + A@W)  (no bias);  else C = act(A@W + bias)
__device__ __noinline__ void gemm64u(
    float* us, int ut, int barid, int amode,
    const float* __restrict__ A0, const float* __restrict__ A1, const float* __restrict__ A2,
    int k0, int k1,
    const float* __restrict__ W, const float* __restrict__ bias, int N,
    float* __restrict__ C, int ldc, int row0, int col0, int act, int accum)
{
    const int tx = ut & 15, ty = ut >> 4;
    const int KT = (k0 + k1) >> 5;

    unsigned long long acc[4][4];
#pragma unroll
    for (int i = 0; i < 4; i++)
#pragma unroll
        for (int j = 0; j < 4; j++) acc[i][j] = 0ULL;

    float4 ra[4], rb[4];

    auto ldA = [&](int kb, int l) -> float4 {
        int idx = ut + (l << 7);
        int r = row0 + (idx >> 3);
        int k = kb + ((idx & 7) << 2);
        if (amode == 2) {
            int o = r * k0 + k;
            float4 a = *(const float4*)(A0 + o);
            float4 s = *(const float4*)(A1 + o);
            float4 m = *(const float4*)(A2 + o);
            return make_float4(fmaf(a.x, s.x, m.x), fmaf(a.y, s.y, m.y),
                               fmaf(a.z, s.z, m.z), fmaf(a.w, s.w, m.w));
        } else if (k < k0) {
            return *(const float4*)(A0 + (size_t)r * k0 + k);
        } else {
            return *(const float4*)(A1 + (size_t)r * k1 + (k - k0));
        }
    };
    auto ldB = [&](int kb, int l) -> float4 {
        int idx = ut + (l << 7);
        int k = kb + (idx >> 4);
        int n = col0 + ((idx & 15) << 2);
        return *(const float4*)(W + (size_t)k * N + n);
    };
    auto stAll = [&](float* buf) {
        float* As = buf;
        float* Bs = buf + AS_SZ;
#pragma unroll
        for (int l = 0; l < 4; l++) {
            int idx = ut + (l << 7);
            int r = idx >> 3, kq = (idx & 7) << 2;
            float4 v = ra[l];
            As[(kq + 0) * AS_STRIDE + r] = v.x;
            As[(kq + 1) * AS_STRIDE + r] = v.y;
            As[(kq + 2) * AS_STRIDE + r] = v.z;
            As[(kq + 3) * AS_STRIDE + r] = v.w;
            int k = idx >> 4, n4 = (idx & 15) << 2;
            *(float4*)(Bs + k * BS_STRIDE + n4) = rb[l];
        }
    };

    // prologue
#pragma unroll
    for (int l = 0; l < 4; l++) { ra[l] = ldA(0, l); rb[l] = ldB(0, l); }
    stAll(us);
    ubar(barid);

    int cur = 0;
    for (int kt = 0; kt < KT; kt++) {
        if (kt + 1 < KT) {
            int kb = (kt + 1) << 5;
#pragma unroll
            for (int l = 0; l < 4; l++) { ra[l] = ldA(kb, l); rb[l] = ldB(kb, l); }
        }
        const float* As = us + cur * BUF_SZ;
        const float* Bs = As + AS_SZ;
#pragma unroll 8
        for (int kk = 0; kk < 32; kk++) {
            float4 a0 = *(const float4*)(As + kk * AS_STRIDE + 8 * ty);
            float4 a1 = *(const float4*)(As + kk * AS_STRIDE + 8 * ty + 4);
            float4 b  = *(const float4*)(Bs + kk * BS_STRIDE + 4 * tx);
            unsigned long long A01 = pk2(a0.x, a0.y);
            unsigned long long A23 = pk2(a0.z, a0.w);
            unsigned long long A45 = pk2(a1.x, a1.y);
            unsigned long long A67 = pk2(a1.z, a1.w);
            unsigned long long B0 = pk2(b.x, b.x);
            unsigned long long B1 = pk2(b.y, b.y);
            unsigned long long B2 = pk2(b.z, b.z);
            unsigned long long B3 = pk2(b.w, b.w);
            ffma2(acc[0][0], A01, B0); ffma2(acc[1][0], A23, B0);
            ffma2(acc[2][0], A45, B0); ffma2(acc[3][0], A67, B0);
            ffma2(acc[0][1], A01, B1); ffma2(acc[1][1], A23, B1);
            ffma2(acc[2][1], A45, B1); ffma2(acc[3][1], A67, B1);
            ffma2(acc[0][2], A01, B2); ffma2(acc[1][2], A23, B2);
            ffma2(acc[2][2], A45, B2); ffma2(acc[3][2], A67, B2);
            ffma2(acc[0][3], A01, B3); ffma2(acc[1][3], A23, B3);
            ffma2(acc[2][3], A45, B3); ffma2(acc[3][3], A67, B3);
        }
        if (kt + 1 < KT) stAll(us + (cur ^ 1) * BUF_SZ);
        ubar(barid);
        cur ^= 1;
    }

    // epilogue
    float4 b4 = accum ? make_float4(0.f, 0.f, 0.f, 0.f)
                      : *(const float4*)(bias + col0 + 4 * tx);
#pragma unroll
    for (int i = 0; i < 4; i++) {
        float2 u0 = upk2(acc[i][0]), u1 = upk2(acc[i][1]);
        float2 u2 = upk2(acc[i][2]), u3 = upk2(acc[i][3]);
        float* c0 = C + (size_t)(row0 + 8 * ty + 2 * i) * ldc + col0 + 4 * tx;
        float* c1 = c0 + ldc;
        float4 oA = make_float4(u0.x + b4.x, u1.x + b4.y, u2.x + b4.z, u3.x + b4.w);
        float4 oB = make_float4(u0.y + b4.x, u1.y + b4.y, u2.y + b4.z, u3.y + b4.w);
        if (accum) {
            float4 e0 = *(float4*)c0, e1 = *(float4*)c1;
            oA.x += e0.x; oA.y += e0.y; oA.z += e0.z; oA.w += e0.w;
            oB.x += e1.x; oB.y += e1.y; oB.z += e1.z; oB.w += e1.w;
        }
        oA.x = actf(oA.x, act); oA.y = actf(oA.y, act); oA.z = actf(oA.z, act); oA.w = actf(oA.w, act);
        oB.x = actf(oB.x, act); oB.y = actf(oB.y, act); oB.z = actf(oB.z, act); oB.w = actf(oB.w, act);
        *(float4*)c0 = oA;
        *(float4*)c1 = oB;
    }
}

// ---------------- params ----------------
struct Params {
    const float *x, *eps;
    const float *pxw1, *pxb1, *pxw2, *pxb2;
    const float *pzw, *pzb;
    const float *ew1, *eb1, *ew2, *eb2, *emw, *emb, *esw, *esb;
    const float *prw, *prb, *pmw, *pmb, *psw, *psb;
    const float *dw1, *db1, *dw2, *db2, *dlw, *dlb;
    const float *gwih, *gbih, *gwhh, *gbhh;
    float *oz, *olog, *oem, *oes, *opm, *ops, *okld;
};

__global__ void __launch_bounds__(NTHR, 1) vrnn_kernel(Params p) {
    extern __shared__ float sm[];
    unsigned gen = 0;
    const int u = threadIdx.x >> 7;        // unit 0..3
    const int ut = threadIdx.x & 127;
    const int barid = u + 1;
    float* us = sm + u * UNIT_SM;
    const int blk = blockIdx.x;
    const int uid = u * NBLK + blk;

    for (int e = blk * NTHR + threadIdx.x; e < B * H; e += NBLK * NTHR) g_h[e] = 0.f;

    // ---- phi_x (all timesteps): 6400 tasks each stage ----
    for (int idx = uid; idx < (T_STEPS * B / 64) * 8; idx += NUNITS) {
        int tm = idx >> 3, tn = idx & 7;
        gemm64u(us, ut, barid, 0, p.x, 0, 0, XD, 0, p.pxw1, p.pxb1, H,
                g_tmp, H, tm * 64, tn * 64, 1, 0);
    }
    gsync(&gen, false);
    for (int idx = uid; idx < (T_STEPS * B / 64) * 8; idx += NUNITS) {
        int tm = idx >> 3, tn = idx & 7;
        gemm64u(us, ut, barid, 0, g_tmp, 0, 0, H, 0, p.pxw2, p.pxb2, H,
                g_phi, H, tm * 64, tn * 64, 1, 0);
    }
    gsync(&gen, false);

    for (int t = 0; t < T_STEPS; t++) {
        const float* px = g_phi + (size_t)t * B * H;
        float* d1 = g_d1b[t & 1];
        const float* d1prev = g_d1b[(t ^ 1) & 1];

        // ---- P1: e1(K=1024) | gh | gx_px | d1_h | pr | d2(t-1) ----
        {
            int nlight = (t > 0) ? 288 : 256;
            int task = -1;               // 0..31 = e1, >=32 = light (task-32)
            if (blk < 32) {
                if (u == 0) task = blk;
                else if (u == 1) task = 32 + blk;
            } else if (u >= 1) {
                int L = 32 + (u - 1) * 116 + (blk - 32);
                if (L < nlight) task = 32 + L;
            }
            if (task >= 0) {
                if (task < 32) {
                    int tm = task >> 3, tn = task & 7;
                    gemm64u(us, ut, barid, 1, px, g_h, 0, H, H, p.ew1, p.eb1, H,
                            g_e1, H, tm * 64, tn * 64, 1, 0);
                } else {
                    int L = task - 32;
                    if (L < 96) {                       // gh
                        int tm = L / 24, tn = L % 24;
                        gemm64u(us, ut, barid, 0, g_h, 0, 0, H, 0, p.gwhh, p.gbhh, G3,
                                g_gh, G3, tm * 64, tn * 64, 0, 0);
                    } else if (L < 192) {               // gx_px (top half of gwih)
                        int i = L - 96; int tm = i / 24, tn = i % 24;
                        gemm64u(us, ut, barid, 0, px, 0, 0, H, 0, p.gwih, p.gbih, G3,
                                g_gx, G3, tm * 64, tn * 64, 0, 0);
                    } else if (L < 224) {               // d1_h (bottom half of dw1)
                        int i = L - 192; int tm = i >> 3, tn = i & 7;
                        gemm64u(us, ut, barid, 0, g_h, 0, 0, H, 0, p.dw1 + (size_t)H * H, p.db1, H,
                                d1, H, tm * 64, tn * 64, 0, 0);
                    } else if (L < 256) {               // pr
                        int i = L - 224; int tm = i >> 3, tn = i & 7;
                        gemm64u(us, ut, barid, 0, g_h, 0, 0, H, 0, p.prw, p.prb, H,
                                g_pr, H, tm * 64, tn * 64, 1, 0);
                    } else {                            // d2(t-1)
                        int i = L - 256; int tm = i >> 3, tn = i & 7;
                        gemm64u(us, ut, barid, 0, d1prev, 0, 0, H, 0, p.dw2, p.db2, H,
                                g_d2, H, tm * 64, tn * 64, 1, 0);
                    }
                }
            }
            gsync(&gen, false);
        }
        // ---- P2: e2(32) | pm(4) | ps(4) | logits(t-1)(16) ----
        {
            int nt = 40 + (t > 0 ? 16 : 0);
            int idx = uid;
            if (idx < nt) {
                if (idx < 32) {
                    int tm = idx >> 3, tn = idx & 7;
                    gemm64u(us, ut, barid, 0, g_e1, 0, 0, H, 0, p.ew2, p.eb2, H,
                            g_e2, H, tm * 64, tn * 64, 1, 0);
                } else if (idx < 36) {
                    gemm64u(us, ut, barid, 0, g_pr, 0, 0, H, 0, p.pmw, p.pmb, ZD,
                            p.opm + (size_t)t * B * ZD, ZD, (idx - 32) * 64, 0, 0, 0);
                } else if (idx < 40) {
                    gemm64u(us, ut, barid, 0, g_pr, 0, 0, H, 0, p.psw, p.psb, ZD,
                            p.ops + (size_t)t * B * ZD, ZD, (idx - 36) * 64, 0, 2, 0);
                } else {
                    int i = idx - 40; int tm = i >> 2, tn = i & 3;
                    gemm64u(us, ut, barid, 0, g_d2, 0, 0, H, 0, p.dlw, p.dlb, OD,
                            p.olog + (size_t)(t - 1) * B * OD, OD, tm * 64, tn * 64, 0, 0);
                }
            }
            gsync(&gen, false);
        }
        // ---- P3: em(4) | es(4) ----
        {
            int idx = uid;
            if (idx < 8) {
                if (idx < 4)
                    gemm64u(us, ut, barid, 0, g_e2, 0, 0, H, 0, p.emw, p.emb, ZD,
                            p.oem + (size_t)t * B * ZD, ZD, idx * 64, 0, 0, 0);
                else
                    gemm64u(us, ut, barid, 0, g_e2, 0, 0, H, 0, p.esw, p.esb, ZD,
                            p.oes + (size_t)t * B * ZD, ZD, (idx - 4) * 64, 0, 2, 0);
            }
            gsync(&gen, false);
        }
        // ---- P4: pz(32, K=64 fused z) | z+kld(4) ----
        {
            const float* eps_t = p.eps + (size_t)t * B * ZD;
            const float* em_t = p.oem + (size_t)t * B * ZD;
            const float* es_t = p.oes + (size_t)t * B * ZD;
            const float* pm_t = p.opm + (size_t)t * B * ZD;
            const float* ps_t = p.ops + (size_t)t * B * ZD;
            float* z_t = p.oz + (size_t)t * B * ZD;
            float* kld_t = p.okld + (size_t)t * B * ZD;
            int idx = uid;
            if (idx < 36) {
                if (idx < 32) {
                    int tm = idx >> 3, tn = idx & 7;
                    gemm64u(us, ut, barid, 2, eps_t, es_t, em_t, ZD, 0, p.pzw, p.pzb, H,
                            g_pz, H, tm * 64, tn * 64, 1, 0);
                } else {
                    int r0 = (idx - 32) * 64;
                    for (int e = ut; e < 64 * ZD; e += UT) {
                        int o = (r0 + (e >> 6)) * ZD + (e & 63);
                        float em = em_t[o], es = es_t[o], pm = pm_t[o], ps = ps_t[o];
                        z_t[o] = eps_t[o] * es + em;
                        float d = em - pm;
                        kld_t[o] = 0.5f * (2.f * logf(ps) - 2.f * logf(es)
                                           + (es * es + d * d) / (ps * ps) - 1.f);
                    }
                }
            }
            gsync(&gen, false);
        }
        // ---- P5: gx += pz@gwih_bot (96) | d1 = relu(d1 + pz@dw1_top) (32) ----
        {
            int idx = uid;
            if (idx < 128) {
                if (idx < 96) {
                    int tm = idx / 24, tn = idx % 24;
                    gemm64u(us, ut, barid, 0, g_pz, 0, 0, H, 0, p.gwih + (size_t)H * G3, 0, G3,
                            g_gx, G3, tm * 64, tn * 64, 0, 1);
                } else {
                    int i = idx - 96; int tm = i >> 3, tn = i & 7;
                    gemm64u(us, ut, barid, 0, g_pz, 0, 0, H, 0, p.dw1, 0, H,
                            d1, H, tm * 64, tn * 64, 1, 1);
                }
            }
            gsync(&gen, false);
        }
        // ---- P6: GRU h update (16) ----
        {
            int idx = uid;
            if (idx < 16) {
                int base = idx * 8192;
                for (int e = base + ut; e < base + 8192; e += UT) {
                    int b = e >> 9, j = e & 511;
                    float xr = g_gx[b * G3 + j], xz = g_gx[b * G3 + 512 + j], xn = g_gx[b * G3 + 1024 + j];
                    float hr = g_gh[b * G3 + j], hz = g_gh[b * G3 + 512 + j], hn = g_gh[b * G3 + 1024 + j];
                    float rg = 1.f / (1.f + expf(-(xr + hr)));
                    float ug = 1.f / (1.f + expf(-(xz + hz)));
                    float ng = tanhf(xn + rg * hn);
                    g_h[e] = (1.f - ug) * ng + ug * g_h[e];
                }
            }
            gsync(&gen, false);
        }
    }
    // ---- tail: d2(199), then logits(199) ----
    {
        int idx = uid;
        if (idx < 32) {
            int tm = idx >> 3, tn = idx & 7;
            gemm64u(us, ut, barid, 0, g_d1b[(T_STEPS - 1) & 1], 0, 0, H, 0, p.dw2, p.db2, H,
                    g_d2, H, tm * 64, tn * 64, 1, 0);
        }
        gsync(&gen, false);
        if (idx < 16) {
            int tm = idx >> 2, tn = idx & 3;
            gemm64u(us, ut, barid, 0, g_d2, 0, 0, H, 0, p.dlw, p.dlb, OD,
                    p.olog + (size_t)(T_STEPS - 1) * B * OD, OD, tm * 64, tn * 64, 0, 0);
        }
    }
    gsync(&gen, true);
}

extern "C" void kernel_launch(void* const* d_in, const int* in_sizes, int n_in,
                              void* d_out, int out_size) {
    Params p;
    p.x    = (const float*)d_in[0];
    p.eps  = (const float*)d_in[1];
    p.pxw1 = (const float*)d_in[2];  p.pxb1 = (const float*)d_in[3];
    p.pxw2 = (const float*)d_in[4];  p.pxb2 = (const float*)d_in[5];
    p.pzw  = (const float*)d_in[6];  p.pzb  = (const float*)d_in[7];
    p.ew1  = (const float*)d_in[8];  p.eb1  = (const float*)d_in[9];
    p.ew2  = (const float*)d_in[10]; p.eb2  = (const float*)d_in[11];
    p.emw  = (const float*)d_in[12]; p.emb  = (const float*)d_in[13];
    p.esw  = (const float*)d_in[14]; p.esb  = (const float*)d_in[15];
    p.prw  = (const float*)d_in[16]; p.prb  = (const float*)d_in[17];
    p.pmw  = (const float*)d_in[18]; p.pmb  = (const float*)d_in[19];
    p.psw  = (const float*)d_in[20]; p.psb  = (const float*)d_in[21];
    p.dw1  = (const float*)d_in[22]; p.db1  = (const float*)d_in[23];
    p.dw2  = (const float*)d_in[24]; p.db2  = (const float*)d_in[25];
    p.dlw  = (const float*)d_in[26]; p.dlb  = (const float*)d_in[27];
    if (in_sizes[29] == 3 * H) {
        p.gwih = (const float*)d_in[28]; p.gbih = (const float*)d_in[29];
        p.gwhh = (const float*)d_in[30]; p.gbhh = (const float*)d_in[31];
    } else {
        p.gwih = (const float*)d_in[28]; p.gwhh = (const float*)d_in[29];
        p.gbih = (const float*)d_in[30]; p.gbhh = (const float*)d_in[31];
    }

    float* o = (float*)d_out;
    size_t TBZ = (size_t)T_STEPS * B * ZD;
    size_t TBO = (size_t)T_STEPS * B * OD;
    p.oz   = o;
    p.olog = o + TBZ;
    p.oem  = p.olog + TBO;
    p.oes  = p.oem + TBZ;
    p.opm  = p.oes + TBZ;
    p.ops  = p.opm + TBZ;
    p.okld = p.ops + TBZ;

    static bool attr_set = false;
    if (!attr_set) {
        cudaFuncSetAttribute(vrnn_kernel, cudaFuncAttributeMaxDynamicSharedMemorySize, SMEM_BYTES);
        attr_set = true;
    }
    vrnn_kernel<<<NBLK, NTHR, SMEM_BYTES>>>(p);
}

// round 5
// speedup vs baseline: 1.0180x; 1.0180x over previous
#include <cuda_runtime.h>
#include <math.h>

#define T_STEPS 200
#define B 256
#define XD 128
#define H 512
#define ZD 64
#define OD 256
#define G3 1536
#define NBLK 148
#define NTHR 512
#define UN 4
#define UT 128
#define NUNITS (NBLK * UN)   // 592

// per-unit smem tile geometry (floats)
#define AS_STRIDE 68
#define BS_STRIDE 68
#define AS_SZ (32 * AS_STRIDE)
#define BS_SZ (32 * BS_STRIDE)
#define BUF_SZ (AS_SZ + BS_SZ)               // 4352 floats
#define UNIT_SM (2 * BUF_SZ)                 // double buffered
#define SMEM_BYTES (UN * UNIT_SM * 4)        // ~139.3 KB

// ---------------- scratch ----------------
__device__ float g_phi[(size_t)T_STEPS * B * H];
__device__ float g_tmp[(size_t)T_STEPS * B * H];
__device__ float g_h [B * H];
__device__ float g_pr[B * H];
__device__ float g_e1[B * H];
__device__ float g_e2[B * H];
__device__ float g_pz[B * H];
__device__ float g_d1b[2][B * H];
__device__ float g_d2[B * H];
__device__ float g_gx[B * G3];
__device__ float g_gh[B * G3];

// ---------------- grid barrier ----------------
__device__ unsigned int g_bar = 0;
__device__ volatile unsigned int g_sense = 0;

__device__ __forceinline__ void gsync(unsigned* gen, bool last) {
    __syncthreads();
    if (threadIdx.x == 0) {
        __threadfence();
        unsigned g = *gen;
        if (atomicAdd(&g_bar, 1u) == (unsigned)(NBLK - 1)) {
            g_bar = 0u;
            __threadfence();
            g_sense = last ? 0u : (g + 1u);
        } else {
            while (g_sense == g) { __nanosleep(32); }
            __threadfence();
        }
    }
    __syncthreads();
    (*gen)++;
}

__device__ __forceinline__ void ubar(int id) {
    asm volatile("bar.sync %0, %1;" :: "r"(id), "r"(UT) : "memory");
}

// ---------------- helpers ----------------
__device__ __forceinline__ unsigned long long pk2(float x, float y) {
    unsigned long long r;
    asm("mov.b64 %0, {%1,%2};" : "=l"(r) : "f"(x), "f"(y));
    return r;
}
__device__ __forceinline__ float2 upk2(unsigned long long v) {
    float2 r;
    asm("mov.b64 {%0,%1}, %2;" : "=f"(r.x), "=f"(r.y) : "l"(v));
    return r;
}
__device__ __forceinline__ void ffma2(unsigned long long& d, unsigned long long a, unsigned long long b) {
    asm("fma.rn.f32x2 %0, %1, %2, %0;" : "+l"(d) : "l"(a), "l"(b));
}
__device__ __forceinline__ float actf(float v, int act) {
    if (act == 1) return fmaxf(v, 0.f);
    if (act == 2) return fmaxf(v, 0.f) + log1pf(expf(-fabsf(v)));
    return v;
}

// ---------------- 64x64 tile GEMM on a 128-thread unit ----------------
// per-thread: 8 rows x 4 cols. amode 0 plain / 1 concat / 2 z=eps*es+em.
// accum: C = act(C_old + A@W)  (no bias);  else C = act(A@W + bias)
__device__ __noinline__ void gemm64u(
    float* us, int ut, int barid, int amode,
    const float* __restrict__ A0, const float* __restrict__ A1, const float* __restrict__ A2,
    int k0, int k1,
    const float* __restrict__ W, const float* __restrict__ bias, int N,
    float* __restrict__ C, int ldc, int row0, int col0, int act, int accum)
{
    const int tx = ut & 15, ty = ut >> 4;
    const int KT = (k0 + k1) >> 5;

    unsigned long long acc[4][4];
#pragma unroll
    for (int i = 0; i < 4; i++)
#pragma unroll
        for (int j = 0; j < 4; j++) acc[i][j] = 0ULL;

    float4 ra[4], rb[4];

    auto ldA = [&](int kb, int l) -> float4 {
        int idx = ut + (l << 7);
        int r = row0 + (idx >> 3);
        int k = kb + ((idx & 7) << 2);
        if (amode == 2) {
            int o = r * k0 + k;
            float4 a = *(const float4*)(A0 + o);
            float4 s = *(const float4*)(A1 + o);
            float4 m = *(const float4*)(A2 + o);
            return make_float4(fmaf(a.x, s.x, m.x), fmaf(a.y, s.y, m.y),
                               fmaf(a.z, s.z, m.z), fmaf(a.w, s.w, m.w));
        } else if (k < k0) {
            return *(const float4*)(A0 + (size_t)r * k0 + k);
        } else {
            return *(const float4*)(A1 + (size_t)r * k1 + (k - k0));
        }
    };
    auto ldB = [&](int kb, int l) -> float4 {
        int idx = ut + (l << 7);
        int k = kb + (idx >> 4);
        int n = col0 + ((idx & 15) << 2);
        return *(const float4*)(W + (size_t)k * N + n);
    };
    auto stAll = [&](float* buf) {
        float* As = buf;
        float* Bs = buf + AS_SZ;
#pragma unroll
        for (int l = 0; l < 4; l++) {
            int idx = ut + (l << 7);
            int r = idx >> 3, kq = (idx & 7) << 2;
            float4 v = ra[l];
            As[(kq + 0) * AS_STRIDE + r] = v.x;
            As[(kq + 1) * AS_STRIDE + r] = v.y;
            As[(kq + 2) * AS_STRIDE + r] = v.z;
            As[(kq + 3) * AS_STRIDE + r] = v.w;
            int k = idx >> 4, n4 = (idx & 15) << 2;
            *(float4*)(Bs + k * BS_STRIDE + n4) = rb[l];
        }
    };

    // prologue
#pragma unroll
    for (int l = 0; l < 4; l++) { ra[l] = ldA(0, l); rb[l] = ldB(0, l); }
    stAll(us);
    ubar(barid);

    int cur = 0;
    for (int kt = 0; kt < KT; kt++) {
        if (kt + 1 < KT) {
            int kb = (kt + 1) << 5;
#pragma unroll
            for (int l = 0; l < 4; l++) { ra[l] = ldA(kb, l); rb[l] = ldB(kb, l); }
        }
        const float* As = us + cur * BUF_SZ;
        const float* Bs = As + AS_SZ;
#pragma unroll 8
        for (int kk = 0; kk < 32; kk++) {
            float4 a0 = *(const float4*)(As + kk * AS_STRIDE + 8 * ty);
            float4 a1 = *(const float4*)(As + kk * AS_STRIDE + 8 * ty + 4);
            float4 b  = *(const float4*)(Bs + kk * BS_STRIDE + 4 * tx);
            unsigned long long A01 = pk2(a0.x, a0.y);
            unsigned long long A23 = pk2(a0.z, a0.w);
            unsigned long long A45 = pk2(a1.x, a1.y);
            unsigned long long A67 = pk2(a1.z, a1.w);
            unsigned long long B0 = pk2(b.x, b.x);
            unsigned long long B1 = pk2(b.y, b.y);
            unsigned long long B2 = pk2(b.z, b.z);
            unsigned long long B3 = pk2(b.w, b.w);
            ffma2(acc[0][0], A01, B0); ffma2(acc[1][0], A23, B0);
            ffma2(acc[2][0], A45, B0); ffma2(acc[3][0], A67, B0);
            ffma2(acc[0][1], A01, B1); ffma2(acc[1][1], A23, B1);
            ffma2(acc[2][1], A45, B1); ffma2(acc[3][1], A67, B1);
            ffma2(acc[0][2], A01, B2); ffma2(acc[1][2], A23, B2);
            ffma2(acc[2][2], A45, B2); ffma2(acc[3][2], A67, B2);
            ffma2(acc[0][3], A01, B3); ffma2(acc[1][3], A23, B3);
            ffma2(acc[2][3], A45, B3); ffma2(acc[3][3], A67, B3);
        }
        if (kt + 1 < KT) stAll(us + (cur ^ 1) * BUF_SZ);
        ubar(barid);
        cur ^= 1;
    }

    // epilogue
    float4 b4 = accum ? make_float4(0.f, 0.f, 0.f, 0.f)
                      : *(const float4*)(bias + col0 + 4 * tx);
#pragma unroll
    for (int i = 0; i < 4; i++) {
        float2 u0 = upk2(acc[i][0]), u1 = upk2(acc[i][1]);
        float2 u2 = upk2(acc[i][2]), u3 = upk2(acc[i][3]);
        float* c0 = C + (size_t)(row0 + 8 * ty + 2 * i) * ldc + col0 + 4 * tx;
        float* c1 = c0 + ldc;
        float4 oA = make_float4(u0.x + b4.x, u1.x + b4.y, u2.x + b4.z, u3.x + b4.w);
        float4 oB = make_float4(u0.y + b4.x, u1.y + b4.y, u2.y + b4.z, u3.y + b4.w);
        if (accum) {
            float4 e0 = *(float4*)c0, e1 = *(float4*)c1;
            oA.x += e0.x; oA.y += e0.y; oA.z += e0.z; oA.w += e0.w;
            oB.x += e1.x; oB.y += e1.y; oB.z += e1.z; oB.w += e1.w;
        }
        oA.x = actf(oA.x, act); oA.y = actf(oA.y, act); oA.z = actf(oA.z, act); oA.w = actf(oA.w, act);
        oB.x = actf(oB.x, act); oB.y = actf(oB.y, act); oB.z = actf(oB.z, act); oB.w = actf(oB.w, act);
        *(float4*)c0 = oA;
        *(float4*)c1 = oB;
    }
}

// ---------------- params ----------------
struct Params {
    const float *x, *eps;
    const float *pxw1, *pxb1, *pxw2, *pxb2;
    const float *pzw, *pzb;
    const float *ew1, *eb1, *ew2, *eb2, *emw, *emb, *esw, *esb;
    const float *prw, *prb, *pmw, *pmb, *psw, *psb;
    const float *dw1, *db1, *dw2, *db2, *dlw, *dlb;
    const float *gwih, *gbih, *gwhh, *gbhh;
    float *oz, *olog, *oem, *oes, *opm, *ops, *okld;
};

__global__ void __launch_bounds__(NTHR, 1) vrnn_kernel(Params p) {
    extern __shared__ float sm[];
    unsigned gen = 0;
    const int u = threadIdx.x >> 7;        // unit 0..3
    const int ut = threadIdx.x & 127;
    const int barid = u + 1;
    float* us = sm + u * UNIT_SM;
    const int blk = blockIdx.x;
    const int uid = u * NBLK + blk;

    for (int e = blk * NTHR + threadIdx.x; e < B * H; e += NBLK * NTHR) g_h[e] = 0.f;

    // ---- phi_x (all timesteps): 6400 tasks each stage ----
    for (int idx = uid; idx < (T_STEPS * B / 64) * 8; idx += NUNITS) {
        int tm = idx >> 3, tn = idx & 7;
        gemm64u(us, ut, barid, 0, p.x, 0, 0, XD, 0, p.pxw1, p.pxb1, H,
                g_tmp, H, tm * 64, tn * 64, 1, 0);
    }
    gsync(&gen, false);
    for (int idx = uid; idx < (T_STEPS * B / 64) * 8; idx += NUNITS) {
        int tm = idx >> 3, tn = idx & 7;
        gemm64u(us, ut, barid, 0, g_tmp, 0, 0, H, 0, p.pxw2, p.pxb2, H,
                g_phi, H, tm * 64, tn * 64, 1, 0);
    }
    gsync(&gen, false);

    for (int t = 0; t < T_STEPS; t++) {
        const float* px = g_phi + (size_t)t * B * H;
        float* d1 = g_d1b[t & 1];
        const float* d1prev = g_d1b[(t ^ 1) & 1];

        // ---- P1: e1(K=1024) | gh | gx_px | d1_h | pr | d2(t-1) ----
        {
            int nlight = (t > 0) ? 288 : 256;
            int task = -1;               // 0..31 = e1, >=32 = light (task-32)
            if (blk < 32) {
                if (u == 0) task = blk;
                else if (u == 1) task = 32 + blk;
            } else if (u >= 1) {
                int L = 32 + (u - 1) * 116 + (blk - 32);
                if (L < nlight) task = 32 + L;
            }
            if (task >= 0) {
                if (task < 32) {
                    int tm = task >> 3, tn = task & 7;
                    gemm64u(us, ut, barid, 1, px, g_h, 0, H, H, p.ew1, p.eb1, H,
                            g_e1, H, tm * 64, tn * 64, 1, 0);
                } else {
                    int L = task - 32;
                    if (L < 96) {                       // gh
                        int tm = L / 24, tn = L % 24;
                        gemm64u(us, ut, barid, 0, g_h, 0, 0, H, 0, p.gwhh, p.gbhh, G3,
                                g_gh, G3, tm * 64, tn * 64, 0, 0);
                    } else if (L < 192) {               // gx_px (top half of gwih)
                        int i = L - 96; int tm = i / 24, tn = i % 24;
                        gemm64u(us, ut, barid, 0, px, 0, 0, H, 0, p.gwih, p.gbih, G3,
                                g_gx, G3, tm * 64, tn * 64, 0, 0);
                    } else if (L < 224) {               // d1_h (bottom half of dw1)
                        int i = L - 192; int tm = i >> 3, tn = i & 7;
                        gemm64u(us, ut, barid, 0, g_h, 0, 0, H, 0, p.dw1 + (size_t)H * H, p.db1, H,
                                d1, H, tm * 64, tn * 64, 0, 0);
                    } else if (L < 256) {               // pr
                        int i = L - 224; int tm = i >> 3, tn = i & 7;
                        gemm64u(us, ut, barid, 0, g_h, 0, 0, H, 0, p.prw, p.prb, H,
                                g_pr, H, tm * 64, tn * 64, 1, 0);
                    } else {                            // d2(t-1)
                        int i = L - 256; int tm = i >> 3, tn = i & 7;
                        gemm64u(us, ut, barid, 0, d1prev, 0, 0, H, 0, p.dw2, p.db2, H,
                                g_d2, H, tm * 64, tn * 64, 1, 0);
                    }
                }
            }
            gsync(&gen, false);
        }
        // ---- P2: e2(32) | pm(4) | ps(4) | logits(t-1)(16) ----
        {
            int nt = 40 + (t > 0 ? 16 : 0);
            int idx = uid;
            if (idx < nt) {
                if (idx < 32) {
                    int tm = idx >> 3, tn = idx & 7;
                    gemm64u(us, ut, barid, 0, g_e1, 0, 0, H, 0, p.ew2, p.eb2, H,
                            g_e2, H, tm * 64, tn * 64, 1, 0);
                } else if (idx < 36) {
                    gemm64u(us, ut, barid, 0, g_pr, 0, 0, H, 0, p.pmw, p.pmb, ZD,
                            p.opm + (size_t)t * B * ZD, ZD, (idx - 32) * 64, 0, 0, 0);
                } else if (idx < 40) {
                    gemm64u(us, ut, barid, 0, g_pr, 0, 0, H, 0, p.psw, p.psb, ZD,
                            p.ops + (size_t)t * B * ZD, ZD, (idx - 36) * 64, 0, 2, 0);
                } else {
                    int i = idx - 40; int tm = i >> 2, tn = i & 3;
                    gemm64u(us, ut, barid, 0, g_d2, 0, 0, H, 0, p.dlw, p.dlb, OD,
                            p.olog + (size_t)(t - 1) * B * OD, OD, tm * 64, tn * 64, 0, 0);
                }
            }
            gsync(&gen, false);
        }
        // ---- P3: em(4) | es(4) ----
        {
            int idx = uid;
            if (idx < 8) {
                if (idx < 4)
                    gemm64u(us, ut, barid, 0, g_e2, 0, 0, H, 0, p.emw, p.emb, ZD,
                            p.oem + (size_t)t * B * ZD, ZD, idx * 64, 0, 0, 0);
                else
                    gemm64u(us, ut, barid, 0, g_e2, 0, 0, H, 0, p.esw, p.esb, ZD,
                            p.oes + (size_t)t * B * ZD, ZD, (idx - 4) * 64, 0, 2, 0);
            }
            gsync(&gen, false);
        }
        // ---- P4: pz(32, K=64 fused z) | z+kld(4) ----
        {
            const float* eps_t = p.eps + (size_t)t * B * ZD;
            const float* em_t = p.oem + (size_t)t * B * ZD;
            const float* es_t = p.oes + (size_t)t * B * ZD;
            const float* pm_t = p.opm + (size_t)t * B * ZD;
            const float* ps_t = p.ops + (size_t)t * B * ZD;
            float* z_t = p.oz + (size_t)t * B * ZD;
            float* kld_t = p.okld + (size_t)t * B * ZD;
            int idx = uid;
            if (idx < 36) {
                if (idx < 32) {
                    int tm = idx >> 3, tn = idx & 7;
                    gemm64u(us, ut, barid, 2, eps_t, es_t, em_t, ZD, 0, p.pzw, p.pzb, H,
                            g_pz, H, tm * 64, tn * 64, 1, 0);
                } else {
                    int r0 = (idx - 32) * 64;
                    for (int e = ut; e < 64 * ZD; e += UT) {
                        int o = (r0 + (e >> 6)) * ZD + (e & 63);
                        float em = em_t[o], es = es_t[o], pm = pm_t[o], ps = ps_t[o];
                        z_t[o] = eps_t[o] * es + em;
                        float d = em - pm;
                        kld_t[o] = 0.5f * (2.f * logf(ps) - 2.f * logf(es)
                                           + (es * es + d * d) / (ps * ps) - 1.f);
                    }
                }
            }
            gsync(&gen, false);
        }
        // ---- P5: gx += pz@gwih_bot (96) | d1 = relu(d1 + pz@dw1_top) (32) ----
        {
            int idx = uid;
            if (idx < 128) {
                if (idx < 96) {
                    int tm = idx / 24, tn = idx % 24;
                    gemm64u(us, ut, barid, 0, g_pz, 0, 0, H, 0, p.gwih + (size_t)H * G3, 0, G3,
                            g_gx, G3, tm * 64, tn * 64, 0, 1);
                } else {
                    int i = idx - 96; int tm = i >> 3, tn = i & 7;
                    gemm64u(us, ut, barid, 0, g_pz, 0, 0, H, 0, p.dw1, 0, H,
                            d1, H, tm * 64, tn * 64, 1, 1);
                }
            }
            gsync(&gen, false);
        }
        // ---- P6: GRU h update (16) ----
        {
            int idx = uid;
            if (idx < 16) {
                int base = idx * 8192;
                for (int e = base + ut; e < base + 8192; e += UT) {
                    int b = e >> 9, j = e & 511;
                    float xr = g_gx[b * G3 + j], xz = g_gx[b * G3 + 512 + j], xn = g_gx[b * G3 + 1024 + j];
                    float hr = g_gh[b * G3 + j], hz = g_gh[b * G3 + 512 + j], hn = g_gh[b * G3 + 1024 + j];
                    float rg = 1.f / (1.f + expf(-(xr + hr)));
                    float ug = 1.f / (1.f + expf(-(xz + hz)));
                    float ng = tanhf(xn + rg * hn);
                    g_h[e] = (1.f - ug) * ng + ug * g_h[e];
                }
            }
            gsync(&gen, false);
        }
    }
    // ---- tail: d2(199), then logits(199) ----
    {
        int idx = uid;
        if (idx < 32) {
            int tm = idx >> 3, tn = idx & 7;
            gemm64u(us, ut, barid, 0, g_d1b[(T_STEPS - 1) & 1], 0, 0, H, 0, p.dw2, p.db2, H,
                    g_d2, H, tm * 64, tn * 64, 1, 0);
        }
        gsync(&gen, false);
        if (idx < 16) {
            int tm = idx >> 2, tn = idx & 3;
            gemm64u(us, ut, barid, 0, g_d2, 0, 0, H, 0, p.dlw, p.dlb, OD,
                    p.olog + (size_t)(T_STEPS - 1) * B * OD, OD, tm * 64, tn * 64, 0, 0);
        }
    }
    gsync(&gen, true);
}

extern "C" void kernel_launch(void* const* d_in, const int* in_sizes, int n_in,
                              void* d_out, int out_size) {
    Params p;
    p.x    = (const float*)d_in[0];
    p.eps  = (const float*)d_in[1];
    p.pxw1 = (const float*)d_in[2];  p.pxb1 = (const float*)d_in[3];
    p.pxw2 = (const float*)d_in[4];  p.pxb2 = (const float*)d_in[5];
    p.pzw  = (const float*)d_in[6];  p.pzb  = (const float*)d_in[7];
    p.ew1  = (const float*)d_in[8];  p.eb1  = (const float*)d_in[9];
    p.ew2  = (const float*)d_in[10]; p.eb2  = (const float*)d_in[11];
    p.emw  = (const float*)d_in[12]; p.emb  = (const float*)d_in[13];
    p.esw  = (const float*)d_in[14]; p.esb  = (const float*)d_in[15];
    p.prw  = (const float*)d_in[16]; p.prb  = (const float*)d_in[17];
    p.pmw  = (const float*)d_in[18]; p.pmb  = (const float*)d_in[19];
    p.psw  = (const float*)d_in[20]; p.psb  = (const float*)d_in[21];
    p.dw1  = (const float*)d_in[22]; p.db1  = (const float*)d_in[23];
    p.dw2  = (const float*)d_in[24]; p.db2  = (const float*)d_in[25];
    p.dlw  = (const float*)d_in[26]; p.dlb  = (const float*)d_in[27];
    if (in_sizes[29] == 3 * H) {
        p.gwih = (const float*)d_in[28]; p.gbih = (const float*)d_in[29];
        p.gwhh = (const float*)d_in[30]; p.gbhh = (const float*)d_in[31];
    } else {
        p.gwih = (const float*)d_in[28]; p.gwhh = (const float*)d_in[29];
        p.gbih = (const float*)d_in[30]; p.gbhh = (const float*)d_in[31];
    }

    float* o = (float*)d_out;
    size_t TBZ = (size_t)T_STEPS * B * ZD;
    size_t TBO = (size_t)T_STEPS * B * OD;
    p.oz   = o;
    p.olog = o + TBZ;
    p.oem  = p.olog + TBO;
    p.oes  = p.oem + TBZ;
    p.opm  = p.oes + TBZ;
    p.ops  = p.opm + TBZ;
    p.okld = p.ops + TBZ;

    static bool attr_set = false;
    if (!attr_set) {
        cudaFuncSetAttribute(vrnn_kernel, cudaFuncAttributeMaxDynamicSharedMemorySize, SMEM_BYTES);
        attr_set = true;
    }
    vrnn_kernel<<<NBLK, NTHR, SMEM_BYTES>>>(p);
}

// round 7
// speedup vs baseline: 1.4773x; 1.4512x over previous
#include <cuda_runtime.h>
#include <cuda_bf16.h>
#include <math.h>
#include <stdint.h>

#define T_STEPS 200
#define B 256
#define XD 128
#define H 512
#define ZD 64
#define OD 256
#define G3 1536
#define NBLK 148
#define NTHR 256

// smem buffers (halfword units): per buffer Ah|Al|Wh|Wl, 128 rows x 72 stride each
#define AST 72
#define A_L 9216
#define W_H 18432
#define W_L 27648
#define BUF_H 36864
#define SM_TILES 1024
#define SMEM_BYTES (SM_TILES + 2 * BUF_H * 2)

// transposed bf16 weight offsets ([N][K] layout, element counts)
#define OFF_PXW1 0
#define OFF_PXW2 65536
#define OFF_PZW  327680
#define OFF_EW1  360448
#define OFF_EW2  884736
#define OFF_EMW  1146880
#define OFF_ESW  1179648
#define OFF_PRW  1212416
#define OFF_PMW  1474560
#define OFF_PSW  1507328
#define OFF_DW1  1540096
#define OFF_DW2  2064384
#define OFF_DLW  2326528
#define OFF_GWIH 2457600
#define OFF_GWHH 4030464
#define W_TOTAL  4816896

// ---------------- scratch ----------------
__device__ float g_phi[(size_t)T_STEPS * B * H];
__device__ float g_e1pre[(size_t)T_STEPS * B * H];
__device__ float g_h [B * H];
__device__ float g_pr[B * H];
__device__ float g_e1[B * H];
__device__ float g_e2[B * H];
__device__ float g_pz[B * H];
__device__ float g_d1b[2][B * H];
__device__ float g_d2[B * H];
__device__ float g_gx[B * G3];
__device__ float g_gh[B * G3];
__device__ __align__(16) __nv_bfloat16 g_whi[W_TOTAL];
__device__ __align__(16) __nv_bfloat16 g_wlo[W_TOTAL];

// ---------------- grid barrier ----------------
__device__ unsigned int g_bar = 0;
__device__ volatile unsigned int g_sense = 0;

__device__ __forceinline__ void gsync(unsigned* gen, bool last) {
    __syncthreads();
    if (threadIdx.x == 0) {
        __threadfence();
        unsigned g = *gen;
        if (atomicAdd(&g_bar, 1u) == (unsigned)(NBLK - 1)) {
            g_bar = 0u;
            __threadfence();
            g_sense = last ? 0u : (g + 1u);
        } else {
            while (g_sense == g) { __nanosleep(32); }
            __threadfence();
        }
    }
    __syncthreads();
    (*gen)++;
}

// ---------------- helpers ----------------
__device__ __forceinline__ uint32_t smem_u32(const void* p) {
    uint32_t a;
    asm("{ .reg .u64 t; cvta.to.shared.u64 t, %1; cvt.u32.u64 %0, t; }" : "=r"(a) : "l"(p));
    return a;
}
__device__ __forceinline__ void ldsm4(uint32_t* r, uint32_t addr) {
    asm volatile("ldmatrix.sync.aligned.m8n8.x4.shared.b16 {%0,%1,%2,%3}, [%4];"
                 : "=r"(r[0]), "=r"(r[1]), "=r"(r[2]), "=r"(r[3]) : "r"(addr));
}
__device__ __forceinline__ void mma16816(float* d, const uint32_t* a, const uint32_t* b) {
    asm volatile(
        "mma.sync.aligned.m16n8k16.row.col.f32.bf16.bf16.f32 "
        "{%0,%1,%2,%3}, {%4,%5,%6,%7}, {%8,%9}, {%0,%1,%2,%3};"
        : "+f"(d[0]), "+f"(d[1]), "+f"(d[2]), "+f"(d[3])
        : "r"(a[0]), "r"(a[1]), "r"(a[2]), "r"(a[3]), "r"(b[0]), "r"(b[1]));
}
__device__ __forceinline__ float actf(float v, int act) {
    if (act == 1) return fmaxf(v, 0.f);
    if (act == 2) return fmaxf(v, 0.f) + log1pf(expf(-fabsf(v)));
    return v;
}
__device__ __forceinline__ uint32_t bpack(float a, float b) {
    __nv_bfloat162 h = __floats2bfloat162_rn(a, b);
    return *(uint32_t*)&h;
}

// ---------------- mma.sync 128 x (NT*16) GEMM tile ----------------
// C[row0:+128, col0:+NT*16] = act( A @ Wt^T + bias [+ accsrc] )
// A fp32 (split hi/lo on the fly). Wt: pre-split bf16 [N][K] at woff, row stride ldw,
// col shift kbase. amode 0: A=A0[.,k0]; amode 2: A = A0*A1+A2 (K=k0).
template<int NT>
__device__ __noinline__ void gemmT(
    char* smc, int row0, int col0, int amode,
    const float* __restrict__ A0, const float* __restrict__ A1, const float* __restrict__ A2,
    int k0, int woff, int ldw, int kbase,
    const float* __restrict__ bias, const float* __restrict__ accsrc,
    float* __restrict__ C, int ldc, int act)
{
    const int tid = threadIdx.x;
    const int lane = tid & 31, wid = tid >> 5;
    const int wm = wid & 3, wn = wid >> 2;
    const int NC = k0 >> 6;
    const uint32_t smb = smem_u32(smc) + SM_TILES;

    float acc[2][NT][4];
#pragma unroll
    for (int i = 0; i < 2; i++)
#pragma unroll
        for (int j = 0; j < NT; j++)
#pragma unroll
            for (int q = 0; q < 4; q++) acc[i][j][q] = 0.f;

    auto stage = [&](int b, int kb) {
        uint16_t* bb = (uint16_t*)(smc + SM_TILES) + b * BUF_H;
        // A: 128 rows x 64 k
#pragma unroll 2
        for (int it = tid; it < 1024; it += NTHR) {
            int r = it >> 3, kg = (it & 7) << 3;
            float v[8];
            if (amode == 2) {
                size_t o = (size_t)(row0 + r) * k0 + kb + kg;
                float4 a0 = *(const float4*)(A0 + o), a1 = *(const float4*)(A0 + o + 4);
                float4 s0 = *(const float4*)(A1 + o), s1 = *(const float4*)(A1 + o + 4);
                float4 m0 = *(const float4*)(A2 + o), m1 = *(const float4*)(A2 + o + 4);
                v[0] = fmaf(a0.x, s0.x, m0.x); v[1] = fmaf(a0.y, s0.y, m0.y);
                v[2] = fmaf(a0.z, s0.z, m0.z); v[3] = fmaf(a0.w, s0.w, m0.w);
                v[4] = fmaf(a1.x, s1.x, m1.x); v[5] = fmaf(a1.y, s1.y, m1.y);
                v[6] = fmaf(a1.z, s1.z, m1.z); v[7] = fmaf(a1.w, s1.w, m1.w);
            } else {
                const float* s = A0 + (size_t)(row0 + r) * k0 + kb + kg;
                float4 x0 = *(const float4*)s, x1 = *(const float4*)(s + 4);
                v[0] = x0.x; v[1] = x0.y; v[2] = x0.z; v[3] = x0.w;
                v[4] = x1.x; v[5] = x1.y; v[6] = x1.z; v[7] = x1.w;
            }
            uint32_t hw[4], lw[4];
#pragma unroll
            for (int j = 0; j < 4; j++) {
                float h0 = __bfloat162float(__float2bfloat16(v[2 * j]));
                float h1 = __bfloat162float(__float2bfloat16(v[2 * j + 1]));
                hw[j] = bpack(v[2 * j], v[2 * j + 1]);
                lw[j] = bpack(v[2 * j] - h0, v[2 * j + 1] - h1);
            }
            *(uint4*)(bb + r * AST + kg) = make_uint4(hw[0], hw[1], hw[2], hw[3]);
            *(uint4*)(bb + A_L + r * AST + kg) = make_uint4(lw[0], lw[1], lw[2], lw[3]);
        }
        // W: NT*16 rows x 64 k
#pragma unroll 2
        for (int it = tid; it < NT * 128; it += NTHR) {
            int r = it >> 3, kg = (it & 7) << 3;
            size_t o = (size_t)woff + (size_t)(col0 + r) * ldw + kbase + kb + kg;
            *(uint4*)(bb + W_H + r * AST + kg) = *(const uint4*)(g_whi + o);
            *(uint4*)(bb + W_L + r * AST + kg) = *(const uint4*)(g_wlo + o);
        }
    };

    const int arow = wm * 32 + (lane & 15);
    const int acolh = (lane >> 4) << 3;
    const int brow = ((lane >> 4) << 3) + (lane & 7);
    const int bko = ((lane >> 3) & 1) << 3;

    stage(0, 0);
    __syncthreads();

    for (int c = 0; c < NC; c++) {
        if (c + 1 < NC) stage((c + 1) & 1, (c + 1) << 6);
        uint32_t bufb = smb + (uint32_t)(c & 1) * (BUF_H * 2);
#pragma unroll
        for (int ks = 0; ks < 4; ks++) {
            uint32_t ah[2][4], al[2][4];
#pragma unroll
            for (int mt = 0; mt < 2; mt++) {
                uint32_t ad = bufb + (uint32_t)(((arow + mt * 16) * AST + (ks << 4) + acolh) << 1);
                ldsm4(ah[mt], ad);
                ldsm4(al[mt], ad + (A_L << 1));
            }
#pragma unroll
            for (int ntp = 0; ntp < NT / 2; ntp++) {
                uint32_t bd = bufb + (uint32_t)(((W_H) + (wn * (NT * 8) + ntp * 16 + brow) * AST
                                                 + (ks << 4) + bko) << 1);
                uint32_t bh[4], bl[4];
                ldsm4(bh, bd);
                ldsm4(bl, bd + ((W_L - W_H) << 1));
#pragma unroll
                for (int mt = 0; mt < 2; mt++) {
                    mma16816(acc[mt][2 * ntp],     ah[mt], bh);
                    mma16816(acc[mt][2 * ntp],     ah[mt], bl);
                    mma16816(acc[mt][2 * ntp],     al[mt], bh);
                    mma16816(acc[mt][2 * ntp + 1], ah[mt], bh + 2);
                    mma16816(acc[mt][2 * ntp + 1], ah[mt], bl + 2);
                    mma16816(acc[mt][2 * ntp + 1], al[mt], bh + 2);
                }
            }
        }
        __syncthreads();
    }

    // epilogue (registers -> global)
#pragma unroll
    for (int mt = 0; mt < 2; mt++) {
        int r1 = row0 + wm * 32 + mt * 16 + (lane >> 2);
#pragma unroll
        for (int nt = 0; nt < NT; nt++) {
            int cc = col0 + wn * (NT * 8) + nt * 8 + ((lane & 3) << 1);
            float bx = 0.f, by = 0.f;
            if (bias) { float2 bv = *(const float2*)(bias + cc); bx = bv.x; by = bv.y; }
            float o0 = acc[mt][nt][0] + bx, o1 = acc[mt][nt][1] + by;
            float o2 = acc[mt][nt][2] + bx, o3 = acc[mt][nt][3] + by;
            if (accsrc) {
                float2 a0 = *(const float2*)(accsrc + (size_t)r1 * ldc + cc);
                float2 a1 = *(const float2*)(accsrc + (size_t)(r1 + 8) * ldc + cc);
                o0 += a0.x; o1 += a0.y; o2 += a1.x; o3 += a1.y;
            }
            *(float2*)(C + (size_t)r1 * ldc + cc) =
                make_float2(actf(o0, act), actf(o1, act));
            *(float2*)(C + (size_t)(r1 + 8) * ldc + cc) =
                make_float2(actf(o2, act), actf(o3, act));
        }
    }
}

// ---------------- params ----------------
struct Params {
    const float *x, *eps;
    const float *pxw1, *pxb1, *pxw2, *pxb2;
    const float *pzw, *pzb;
    const float *ew1, *eb1, *ew2, *eb2, *emw, *emb, *esw, *esb;
    const float *prw, *prb, *pmw, *pmb, *psw, *psb;
    const float *dw1, *db1, *dw2, *db2, *dlw, *dlb;
    const float *gwih, *gbih, *gwhh, *gbhh;
    float *oz, *olog, *oem, *oes, *opm, *ops, *okld;
};

__global__ void __launch_bounds__(NTHR, 1) vrnn_kernel(Params p) {
    extern __shared__ char smc[];
    unsigned gen = 0;
    const int tid = threadIdx.x;
    const int blk = blockIdx.x;

    for (int e = blk * NTHR + tid; e < B * H; e += NBLK * NTHR) g_h[e] = 0.f;

#define GEMM8(...) gemmT<8>(smc, __VA_ARGS__)
#define GEMM4(...) gemmT<4>(smc, __VA_ARGS__)

    // ---- weight transpose + bf16 hi/lo split ----
    {
        const float* wsrc[15] = {p.pxw1, p.pxw2, p.pzw, p.ew1, p.ew2, p.emw, p.esw, p.prw,
                                 p.pmw, p.psw, p.dw1, p.dw2, p.dlw, p.gwih, p.gwhh};
        const int wk[15] = {128, 512, 64, 1024, 512, 512, 512, 512, 512, 512, 1024, 512, 512, 1024, 512};
        const int wn[15] = {512, 512, 512, 512, 512, 64, 64, 512, 64, 64, 512, 512, 256, 1536, 1536};
        const int wof[15] = {OFF_PXW1, OFF_PXW2, OFF_PZW, OFF_EW1, OFF_EW2, OFF_EMW, OFF_ESW, OFF_PRW,
                             OFF_PMW, OFF_PSW, OFF_DW1, OFF_DW2, OFF_DLW, OFF_GWIH, OFF_GWHH};
        float* tile = (float*)(smc + SM_TILES);
        for (int task = blk; task < 1176; task += NBLK) {
            int tt = task, w = 0;
            for (; w < 15; w++) {
                int nt = (wk[w] >> 6) * (wn[w] >> 6);
                if (tt < nt) break;
                tt -= nt;
            }
            int tkc = wk[w] >> 6;
            int k0 = (tt % tkc) * 64, n0 = (tt / tkc) * 64;
            const float* src = wsrc[w];
            int K = wk[w], N = wn[w];
            for (int it = tid; it < 4096; it += NTHR) {
                int i = it >> 6, j = it & 63;
                tile[i * 68 + j] = src[(size_t)(k0 + i) * N + n0 + j];
            }
            __syncthreads();
            for (int it = tid; it < 4096; it += NTHR) {
                int j = it >> 6, i = it & 63;
                float v = tile[i * 68 + j];
                __nv_bfloat16 hi = __float2bfloat16(v);
                size_t o = (size_t)wof[w] + (size_t)(n0 + j) * K + k0 + i;
                g_whi[o] = hi;
                g_wlo[o] = __float2bfloat16(v - __bfloat162float(hi));
            }
            __syncthreads();
        }
    }
    gsync(&gen, false);

    // ---- preamble: phi stage1 -> g_e1pre(temp), stage2 -> g_phi, e1 precompute -> g_e1pre ----
    for (int idx = blk; idx < 1600; idx += NBLK) {
        int tm = idx >> 2, tn = idx & 3;
        GEMM8(tm * 128, tn * 128, 0, p.x, 0, 0, XD, OFF_PXW1, XD, 0,
              p.pxb1, 0, g_e1pre, H, 1);
    }
    gsync(&gen, false);
    for (int idx = blk; idx < 1600; idx += NBLK) {
        int tm = idx >> 2, tn = idx & 3;
        GEMM8(tm * 128, tn * 128, 0, g_e1pre, 0, 0, H, OFF_PXW2, H, 0,
              p.pxb2, 0, g_phi, H, 1);
    }
    gsync(&gen, false);
    for (int idx = blk; idx < 1600; idx += NBLK) {
        int tm = idx >> 2, tn = idx & 3;
        GEMM8(tm * 128, tn * 128, 0, g_phi, 0, 0, H, OFF_EW1, 1024, 0,
              p.eb1, 0, g_e1pre, H, 0);
    }
    gsync(&gen, false);

    for (int t = 0; t < T_STEPS; t++) {
        const float* px = g_phi + (size_t)t * B * H;
        const float* e1pre = g_e1pre + (size_t)t * B * H;
        float* d1 = g_d1b[t & 1];
        const float* d1prev = g_d1b[(t + 1) & 1];

        // ---- P1: pr(0-7) gh(8-31) gx_px(32-55) e1(56-63) d1_h(64-71) d2prev(72-79) ----
        {
            int idx = blk;
            if (idx < 8) {
                int tm = idx >> 2, tn = idx & 3;
                GEMM8(tm * 128, tn * 128, 0, g_h, 0, 0, H, OFF_PRW, H, 0,
                      p.prb, 0, g_pr, H, 1);
            } else if (idx < 32) {
                int i = idx - 8; int tm = i / 12, tn = i % 12;
                GEMM8(tm * 128, tn * 128, 0, g_h, 0, 0, H, OFF_GWHH, H, 0,
                      p.gbhh, 0, g_gh, G3, 0);
            } else if (idx < 56) {
                int i = idx - 32; int tm = i / 12, tn = i % 12;
                GEMM8(tm * 128, tn * 128, 0, px, 0, 0, H, OFF_GWIH, 1024, 0,
                      p.gbih, 0, g_gx, G3, 0);
            } else if (idx < 64) {
                int i = idx - 56; int tm = i >> 2, tn = i & 3;
                GEMM8(tm * 128, tn * 128, 0, g_h, 0, 0, H, OFF_EW1, 1024, 512,
                      0, e1pre, g_e1, H, 1);
            } else if (idx < 72) {
                int i = idx - 64; int tm = i >> 2, tn = i & 3;
                GEMM8(tm * 128, tn * 128, 0, g_h, 0, 0, H, OFF_DW1, 1024, 512,
                      p.db1, 0, d1, H, 0);
            } else if (idx < 80 && t > 0) {
                int i = idx - 72; int tm = i >> 2, tn = i & 3;
                GEMM8(tm * 128, tn * 128, 0, d1prev, 0, 0, H, OFF_DW2, H, 0,
                      p.db2, 0, g_d2, H, 1);
            }
            gsync(&gen, false);
        }
        // ---- P2: e2(0-7) pm(8-9) ps(10-11) logits_prev(12-15) ----
        {
            int idx = blk;
            if (idx < 8) {
                int tm = idx >> 2, tn = idx & 3;
                GEMM8(tm * 128, tn * 128, 0, g_e1, 0, 0, H, OFF_EW2, H, 0,
                      p.eb2, 0, g_e2, H, 1);
            } else if (idx < 10) {
                GEMM4((idx - 8) * 128, 0, 0, g_pr, 0, 0, H, OFF_PMW, H, 0,
                      p.pmb, 0, p.opm + (size_t)t * B * ZD, ZD, 0);
            } else if (idx < 12) {
                GEMM4((idx - 10) * 128, 0, 0, g_pr, 0, 0, H, OFF_PSW, H, 0,
                      p.psb, 0, p.ops + (size_t)t * B * ZD, ZD, 2);
            } else if (idx < 16 && t > 0) {
                int i = idx - 12; int tm = i >> 1, tn = i & 1;
                GEMM8(tm * 128, tn * 128, 0, g_d2, 0, 0, H, OFF_DLW, H, 0,
                      p.dlb, 0, p.olog + (size_t)(t - 1) * B * OD, OD, 0);
            }
            gsync(&gen, false);
        }
        // ---- P3: em(0-1) es(2-3) ----
        {
            int idx = blk;
            if (idx < 2) {
                GEMM4(idx * 128, 0, 0, g_e2, 0, 0, H, OFF_EMW, H, 0,
                      p.emb, 0, p.oem + (size_t)t * B * ZD, ZD, 0);
            } else if (idx < 4) {
                GEMM4((idx - 2) * 128, 0, 0, g_e2, 0, 0, H, OFF_ESW, H, 0,
                      p.esb, 0, p.oes + (size_t)t * B * ZD, ZD, 2);
            }
            gsync(&gen, false);
        }
        // ---- P4: pz(0-7, K=64 fused z) | z+kld(8-11) ----
        {
            const float* eps_t = p.eps + (size_t)t * B * ZD;
            const float* em_t = p.oem + (size_t)t * B * ZD;
            const float* es_t = p.oes + (size_t)t * B * ZD;
            int idx = blk;
            if (idx < 8) {
                int tm = idx >> 2, tn = idx & 3;
                GEMM8(tm * 128, tn * 128, 2, eps_t, es_t, em_t, ZD, OFF_PZW, ZD, 0,
                      p.pzb, 0, g_pz, H, 1);
            } else if (idx < 12) {
                const float* pm_t = p.opm + (size_t)t * B * ZD;
                const float* ps_t = p.ops + (size_t)t * B * ZD;
                float* z_t = p.oz + (size_t)t * B * ZD;
                float* kld_t = p.okld + (size_t)t * B * ZD;
                int base = (idx - 8) * 4096;
                for (int e = base + tid; e < base + 4096; e += NTHR) {
                    float em = em_t[e], es = es_t[e], pm = pm_t[e], ps = ps_t[e];
                    z_t[e] = eps_t[e] * es + em;
                    float d = em - pm;
                    kld_t[e] = 0.5f * (2.f * logf(ps) - 2.f * logf(es)
                                       + (es * es + d * d) / (ps * ps) - 1.f);
                }
            }
            gsync(&gen, false);
        }
        // ---- P5: gx += pz@gwih_bot (0-23) | d1 = relu(d1 + pz@dw1_top) (24-31) ----
        {
            int idx = blk;
            if (idx < 24) {
                int tm = idx / 12, tn = idx % 12;
                GEMM8(tm * 128, tn * 128, 0, g_pz, 0, 0, H, OFF_GWIH, 1024, 512,
                      0, g_gx, g_gx, G3, 0);
            } else if (idx < 32) {
                int i = idx - 24; int tm = i >> 2, tn = i & 3;
                GEMM8(tm * 128, tn * 128, 0, g_pz, 0, 0, H, OFF_DW1, 1024, 0,
                      0, d1, d1, H, 1);
            }
            gsync(&gen, false);
        }
        // ---- P6: GRU (0-15) ----
        {
            int idx = blk;
            if (idx < 16) {
                int base = idx * 8192;
                for (int e = base + tid; e < base + 8192; e += NTHR) {
                    int b = e >> 9, j = e & 511;
                    float xr = g_gx[b * G3 + j], xz = g_gx[b * G3 + 512 + j], xn = g_gx[b * G3 + 1024 + j];
                    float hr = g_gh[b * G3 + j], hz = g_gh[b * G3 + 512 + j], hn = g_gh[b * G3 + 1024 + j];
                    float rg = 1.f / (1.f + expf(-(xr + hr)));
                    float ug = 1.f / (1.f + expf(-(xz + hz)));
                    float ng = tanhf(xn + rg * hn);
                    g_h[e] = (1.f - ug) * ng + ug * g_h[e];
                }
            }
            gsync(&gen, false);
        }
    }
    // ---- tail: d2(199), logits(199) ----
    {
        int idx = blk;
        if (idx < 8) {
            int tm = idx >> 2, tn = idx & 3;
            GEMM8(tm * 128, tn * 128, 0, g_d1b[(T_STEPS - 1) & 1], 0, 0, H, OFF_DW2, H, 0,
                  p.db2, 0, g_d2, H, 1);
        }
        gsync(&gen, false);
        if (idx < 4) {
            int tm = idx >> 1, tn = idx & 1;
            GEMM8(tm * 128, tn * 128, 0, g_d2, 0, 0, H, OFF_DLW, H, 0,
                  p.dlb, 0, p.olog + (size_t)(T_STEPS - 1) * B * OD, OD, 0);
        }
    }
    gsync(&gen, true);
}

extern "C" void kernel_launch(void* const* d_in, const int* in_sizes, int n_in,
                              void* d_out, int out_size) {
    Params p;
    p.x    = (const float*)d_in[0];
    p.eps  = (const float*)d_in[1];
    p.pxw1 = (const float*)d_in[2];  p.pxb1 = (const float*)d_in[3];
    p.pxw2 = (const float*)d_in[4];  p.pxb2 = (const float*)d_in[5];
    p.pzw  = (const float*)d_in[6];  p.pzb  = (const float*)d_in[7];
    p.ew1  = (const float*)d_in[8];  p.eb1  = (const float*)d_in[9];
    p.ew2  = (const float*)d_in[10]; p.eb2  = (const float*)d_in[11];
    p.emw  = (const float*)d_in[12]; p.emb  = (const float*)d_in[13];
    p.esw  = (const float*)d_in[14]; p.esb  = (const float*)d_in[15];
    p.prw  = (const float*)d_in[16]; p.prb  = (const float*)d_in[17];
    p.pmw  = (const float*)d_in[18]; p.pmb  = (const float*)d_in[19];
    p.psw  = (const float*)d_in[20]; p.psb  = (const float*)d_in[21];
    p.dw1  = (const float*)d_in[22]; p.db1  = (const float*)d_in[23];
    p.dw2  = (const float*)d_in[24]; p.db2  = (const float*)d_in[25];
    p.dlw  = (const float*)d_in[26]; p.dlb  = (const float*)d_in[27];
    if (in_sizes[29] == 3 * H) {
        p.gwih = (const float*)d_in[28]; p.gbih = (const float*)d_in[29];
        p.gwhh = (const float*)d_in[30]; p.gbhh = (const float*)d_in[31];
    } else {
        p.gwih = (const float*)d_in[28]; p.gwhh = (const float*)d_in[29];
        p.gbih = (const float*)d_in[30]; p.gbhh = (const float*)d_in[31];
    }

    float* o = (float*)d_out;
    size_t TBZ = (size_t)T_STEPS * B * ZD;
    size_t TBO = (size_t)T_STEPS * B * OD;
    p.oz   = o;
    p.olog = o + TBZ;
    p.oem  = p.olog + TBO;
    p.oes  = p.oem + TBZ;
    p.opm  = p.oes + TBZ;
    p.ops  = p.opm + TBZ;
    p.okld = p.ops + TBZ;

    static bool attr_set = false;
    if (!attr_set) {
        cudaFuncSetAttribute(vrnn_kernel, cudaFuncAttributeMaxDynamicSharedMemorySize, SMEM_BYTES);
        attr_set = true;
    }
    vrnn_kernel<<<NBLK, NTHR, SMEM_BYTES>>>(p);
}

// round 9
// speedup vs baseline: 2.2694x; 1.5361x over previous
#include <cuda_runtime.h>
#include <cuda_bf16.h>
#include <math.h>
#include <stdint.h>

#define T_STEPS 200
#define B 256
#define XD 128
#define H 512
#define ZD 64
#define OD 256
#define G3 1536
#define NBLK 148
#define NTHR 512

// smem (halfword units): per buffer Ah|Al|Wh|Wl, each 128 rows x 72 stride
#define AST 72
#define A_L 9216
#define W_H 18432
#define W_L 27648
#define BUF_H 36864
#define SM_TILES 1024
#define SMEM_BYTES (SM_TILES + 2 * BUF_H * 2)

// transposed bf16 weight offsets ([N][K] layout, element counts)
#define OFF_PXW1 0
#define OFF_PXW2 65536
#define OFF_PZW  327680
#define OFF_EW1  360448
#define OFF_EW2  884736
#define OFF_EMW  1146880
#define OFF_ESW  1179648
#define OFF_PRW  1212416
#define OFF_PMW  1474560
#define OFF_PSW  1507328
#define OFF_DW1  1540096
#define OFF_DW2  2064384
#define OFF_DLW  2326528
#define OFF_GWIH 2457600
#define OFF_GWHH 4030464
#define W_TOTAL  4816896

// ---------------- scratch ----------------
__device__ float g_phi[(size_t)T_STEPS * B * H];
__device__ float g_e1pre[(size_t)T_STEPS * B * H];
__device__ float g_gxpre[(size_t)T_STEPS * B * G3];   // px@gwih_top + gbih, all t
__device__ float g_h [B * H];
__device__ float g_pz[B * H];
__device__ float g_prP[2][B * H];
__device__ float g_e1hP[2][B * H];
__device__ float g_d1hP[2][2][B * H];   // [t&1][split]
__device__ float g_d1pzP[2][B * H];
__device__ float g_d2P[2][B * H];
__device__ float g_e2P[2][B * H];
__device__ float g_emP[2][B * ZD];
__device__ float g_esP[2][B * ZD];
__device__ float g_pmP[2][B * ZD];
__device__ float g_psP[2][B * ZD];
__device__ float g_loP[2][B * OD];
__device__ float g_ghP[2][B * G3];
__device__ float g_gxP[2][B * G3];
__device__ __align__(16) __nv_bfloat16 g_whi[W_TOTAL];
__device__ __align__(16) __nv_bfloat16 g_wlo[W_TOTAL];

// ---------------- grid barrier ----------------
__device__ unsigned int g_bar = 0;
__device__ volatile unsigned int g_sense = 0;

__device__ __forceinline__ void gsync(unsigned* gen, bool last) {
    __syncthreads();
    if (threadIdx.x == 0) {
        __threadfence();
        unsigned g = *gen;
        if (atomicAdd(&g_bar, 1u) == (unsigned)(NBLK - 1)) {
            g_bar = 0u;
            __threadfence();
            g_sense = last ? 0u : (g + 1u);
        } else {
            while (g_sense == g) { __nanosleep(32); }
            __threadfence();
        }
    }
    __syncthreads();
    (*gen)++;
}

// ---------------- helpers ----------------
__device__ __forceinline__ uint32_t smem_u32(const void* p) {
    uint32_t a;
    asm("{ .reg .u64 t; cvta.to.shared.u64 t, %1; cvt.u32.u64 %0, t; }" : "=r"(a) : "l"(p));
    return a;
}
__device__ __forceinline__ void ldsm4(uint32_t* r, uint32_t addr) {
    asm volatile("ldmatrix.sync.aligned.m8n8.x4.shared.b16 {%0,%1,%2,%3}, [%4];"
                 : "=r"(r[0]), "=r"(r[1]), "=r"(r[2]), "=r"(r[3]) : "r"(addr));
}
__device__ __forceinline__ void mma16816(float* d, const uint32_t* a, const uint32_t* b) {
    asm volatile(
        "mma.sync.aligned.m16n8k16.row.col.f32.bf16.bf16.f32 "
        "{%0,%1,%2,%3}, {%4,%5,%6,%7}, {%8,%9}, {%0,%1,%2,%3};"
        : "+f"(d[0]), "+f"(d[1]), "+f"(d[2]), "+f"(d[3])
        : "r"(a[0]), "r"(a[1]), "r"(a[2]), "r"(a[3]), "r"(b[0]), "r"(b[1]));
}
__device__ __forceinline__ float actf(float v, int act) {
    if (act == 1) return fmaxf(v, 0.f);
    if (act == 2) return fmaxf(v, 0.f) + log1pf(expf(-fabsf(v)));
    return v;
}
__device__ __forceinline__ float spf(float v) {
    return fmaxf(v, 0.f) + log1pf(expf(-fabsf(v)));
}
__device__ __forceinline__ uint32_t bpack(float a, float b) {
    __nv_bfloat162 h = __floats2bfloat162_rn(a, b);
    return *(uint32_t*)&h;
}

// A-source descriptor: mode 0 plain; 1/2/3 = sum2/3/4 + relu; 5 = eps*sp(es0+es1)+(em0+em1)
struct ASrc {
    const float *s0, *s1, *s2, *s3, *s4;
    int mode;
};
__device__ __forceinline__ void ld8(const float* p, size_t o, float* v) {
    float4 a = *(const float4*)(p + o);
    float4 b = *(const float4*)(p + o + 4);
    v[0] = a.x; v[1] = a.y; v[2] = a.z; v[3] = a.w;
    v[4] = b.x; v[5] = b.y; v[6] = b.z; v[7] = b.w;
}
__device__ __forceinline__ void fetch8(float* v, const ASrc& a, size_t o) {
    ld8(a.s0, o, v);
    if (a.mode == 0) return;
    float w[8];
    if (a.mode == 5) {
        float u[8];
        ld8(a.s1, o, w); ld8(a.s2, o, u);
#pragma unroll
        for (int i = 0; i < 8; i++) w[i] = spf(w[i] + u[i]);     // es
        ld8(a.s3, o, u);
        float m[8]; ld8(a.s4, o, m);
#pragma unroll
        for (int i = 0; i < 8; i++) v[i] = v[i] * w[i] + (u[i] + m[i]);
        return;
    }
    ld8(a.s1, o, w);
#pragma unroll
    for (int i = 0; i < 8; i++) v[i] += w[i];
    if (a.mode >= 2) {
        ld8(a.s2, o, w);
#pragma unroll
        for (int i = 0; i < 8; i++) v[i] += w[i];
    }
    if (a.mode >= 3) {
        ld8(a.s3, o, w);
#pragma unroll
        for (int i = 0; i < 8; i++) v[i] += w[i];
    }
#pragma unroll
    for (int i = 0; i < 8; i++) v[i] = fmaxf(v[i], 0.f);
}

// ---------------- mma.sync 128 x (WN*64) GEMM tile, 16 warps ----------------
// C[row0:+128, col0:+WN*64] = act( A @ Wt^T + bias )
// A via ASrc (fp32, split hi/lo on the fly), row stride k0, k offset akbase, K length klen.
// Wt: pre-split bf16 [N][K] at woff, row stride ldw, col shift wkbase.
template<int WN>
__device__ __noinline__ void gemmT(
    char* smc, int row0, int col0,
    ASrc a, int k0, int akbase, int klen,
    int woff, int ldw, int wkbase,
    const float* __restrict__ bias,
    float* __restrict__ C, int ldc, int act)
{
    const int tid = threadIdx.x;
    const int lane = tid & 31, wid = tid >> 5;
    const int wm = wid & 3, wn = wid >> 2;
    const int NC = klen >> 6;
    const uint32_t smb = smem_u32(smc) + SM_TILES;

    float acc[2][2 * WN][4];
#pragma unroll
    for (int i = 0; i < 2; i++)
#pragma unroll
        for (int j = 0; j < 2 * WN; j++)
#pragma unroll
            for (int q = 0; q < 4; q++) acc[i][j][q] = 0.f;

    auto stage = [&](int b, int kb) {
        uint16_t* bb = (uint16_t*)(smc + SM_TILES) + b * BUF_H;
        // A: 128 rows x 64 k
#pragma unroll 2
        for (int it = tid; it < 1024; it += NTHR) {
            int r = it >> 3, kg = (it & 7) << 3;
            size_t o = (size_t)(row0 + r) * k0 + akbase + kb + kg;
            float v[8];
            fetch8(v, a, o);
            uint32_t hw[4], lw[4];
#pragma unroll
            for (int j = 0; j < 4; j++) {
                float h0 = __bfloat162float(__float2bfloat16(v[2 * j]));
                float h1 = __bfloat162float(__float2bfloat16(v[2 * j + 1]));
                hw[j] = bpack(v[2 * j], v[2 * j + 1]);
                lw[j] = bpack(v[2 * j] - h0, v[2 * j + 1] - h1);
            }
            *(uint4*)(bb + r * AST + kg) = make_uint4(hw[0], hw[1], hw[2], hw[3]);
            *(uint4*)(bb + A_L + r * AST + kg) = make_uint4(lw[0], lw[1], lw[2], lw[3]);
        }
        // W: WN*64 rows x 64 k
#pragma unroll 2
        for (int it = tid; it < WN * 512; it += NTHR) {
            int r = it >> 3, kg = (it & 7) << 3;
            size_t o = (size_t)woff + (size_t)(col0 + r) * ldw + wkbase + kb + kg;
            *(uint4*)(bb + W_H + r * AST + kg) = *(const uint4*)(g_whi + o);
            *(uint4*)(bb + W_L + r * AST + kg) = *(const uint4*)(g_wlo + o);
        }
    };

    const int arow = wm * 32 + (lane & 15);
    const int acolh = (lane >> 4) << 3;
    const int brow = ((lane >> 4) << 3) + (lane & 7);
    const int bko = ((lane >> 3) & 1) << 3;

    stage(0, 0);
    __syncthreads();

    for (int c = 0; c < NC; c++) {
        if (c + 1 < NC) stage((c + 1) & 1, (c + 1) << 6);
        uint32_t bufb = smb + (uint32_t)(c & 1) * (BUF_H * 2);
#pragma unroll
        for (int ks = 0; ks < 4; ks++) {
            uint32_t ah[2][4], al[2][4];
#pragma unroll
            for (int mt = 0; mt < 2; mt++) {
                uint32_t ad = bufb + (uint32_t)(((arow + mt * 16) * AST + (ks << 4) + acolh) << 1);
                ldsm4(ah[mt], ad);
                ldsm4(al[mt], ad + (A_L << 1));
            }
#pragma unroll
            for (int ntp = 0; ntp < WN; ntp++) {
                uint32_t bd = bufb + (uint32_t)((W_H + (wn * (WN * 16) + ntp * 16 + brow) * AST
                                                 + (ks << 4) + bko) << 1);
                uint32_t bh[4], bl[4];
                ldsm4(bh, bd);
                ldsm4(bl, bd + ((W_L - W_H) << 1));
#pragma unroll
                for (int mt = 0; mt < 2; mt++) {
                    mma16816(acc[mt][2 * ntp],     ah[mt], bh);
                    mma16816(acc[mt][2 * ntp],     ah[mt], bl);
                    mma16816(acc[mt][2 * ntp],     al[mt], bh);
                    mma16816(acc[mt][2 * ntp + 1], ah[mt], bh + 2);
                    mma16816(acc[mt][2 * ntp + 1], ah[mt], bl + 2);
                    mma16816(acc[mt][2 * ntp + 1], al[mt], bh + 2);
                }
            }
        }
        __syncthreads();
    }

    // epilogue
#pragma unroll
    for (int mt = 0; mt < 2; mt++) {
        int r1 = row0 + wm * 32 + mt * 16 + (lane >> 2);
#pragma unroll
        for (int nt = 0; nt < 2 * WN; nt++) {
            int cc = col0 + wn * (WN * 16) + nt * 8 + ((lane & 3) << 1);
            float bx = 0.f, by = 0.f;
            if (bias) { float2 bv = *(const float2*)(bias + cc); bx = bv.x; by = bv.y; }
            float o0 = actf(acc[mt][nt][0] + bx, act), o1 = actf(acc[mt][nt][1] + by, act);
            float o2 = actf(acc[mt][nt][2] + bx, act), o3 = actf(acc[mt][nt][3] + by, act);
            *(float2*)(C + (size_t)r1 * ldc + cc) = make_float2(o0, o1);
            *(float2*)(C + (size_t)(r1 + 8) * ldc + cc) = make_float2(o2, o3);
        }
    }
}

// ---------------- params ----------------
struct Params {
    const float *x, *eps;
    const float *pxw1, *pxb1, *pxw2, *pxb2;
    const float *pzw, *pzb;
    const float *ew1, *eb1, *ew2, *eb2, *emw, *emb, *esw, *esb;
    const float *prw, *prb, *pmw, *pmb, *psw, *psb;
    const float *dw1, *db1, *dw2, *db2, *dlw, *dlb;
    const float *gwih, *gbih, *gwhh, *gbhh;
    float *oz, *olog, *oem, *oes, *opm, *ops, *okld;
};

__global__ void __launch_bounds__(NTHR, 1) vrnn_kernel(Params p) {
    extern __shared__ char smc[];
    unsigned gen = 0;
    const int tid = threadIdx.x;
    const int blk = blockIdx.x;

    for (int e = blk * NTHR + tid; e < B * H; e += NBLK * NTHR) g_h[e] = 0.f;

#define PLAIN(ptr) ASrc{ptr, 0, 0, 0, 0, 0}

    // ---- weight transpose + bf16 hi/lo split ----
    {
        const float* wsrc[15] = {p.pxw1, p.pxw2, p.pzw, p.ew1, p.ew2, p.emw, p.esw, p.prw,
                                 p.pmw, p.psw, p.dw1, p.dw2, p.dlw, p.gwih, p.gwhh};
        const int wk[15] = {128, 512, 64, 1024, 512, 512, 512, 512, 512, 512, 1024, 512, 512, 1024, 512};
        const int wn[15] = {512, 512, 512, 512, 512, 64, 64, 512, 64, 64, 512, 512, 256, 1536, 1536};
        const int wof[15] = {OFF_PXW1, OFF_PXW2, OFF_PZW, OFF_EW1, OFF_EW2, OFF_EMW, OFF_ESW, OFF_PRW,
                             OFF_PMW, OFF_PSW, OFF_DW1, OFF_DW2, OFF_DLW, OFF_GWIH, OFF_GWHH};
        float* tile = (float*)(smc + SM_TILES);
        for (int task = blk; task < 1176; task += NBLK) {
            int tt = task, w = 0;
            for (; w < 15; w++) {
                int nt = (wk[w] >> 6) * (wn[w] >> 6);
                if (tt < nt) break;
                tt -= nt;
            }
            int tkc = wk[w] >> 6;
            int k0 = (tt % tkc) * 64, n0 = (tt / tkc) * 64;
            const float* src = wsrc[w];
            int K = wk[w], N = wn[w];
            for (int it = tid; it < 4096; it += NTHR) {
                int i = it >> 6, j = it & 63;
                tile[i * 68 + j] = src[(size_t)(k0 + i) * N + n0 + j];
            }
            __syncthreads();
            for (int it = tid; it < 4096; it += NTHR) {
                int j = it >> 6, i = it & 63;
                float v = tile[i * 68 + j];
                __nv_bfloat16 hi = __float2bfloat16(v);
                size_t o = (size_t)wof[w] + (size_t)(n0 + j) * K + k0 + i;
                g_whi[o] = hi;
                g_wlo[o] = __float2bfloat16(v - __bfloat162float(hi));
            }
            __syncthreads();
        }
    }
    gsync(&gen, false);

    // ---- preamble ----
    // phi stage1 -> g_e1pre (temp)
    for (int idx = blk; idx < 1600; idx += NBLK) {
        int tm = idx >> 2, tn = idx & 3;
        gemmT<2>(smc, tm * 128, tn * 128, PLAIN(p.x), XD, 0, 128,
                 OFF_PXW1, XD, 0, p.pxb1, g_e1pre, H, 1);
    }
    gsync(&gen, false);
    // phi stage2 -> g_phi
    for (int idx = blk; idx < 1600; idx += NBLK) {
        int tm = idx >> 2, tn = idx & 3;
        gemmT<2>(smc, tm * 128, tn * 128, PLAIN(g_e1pre), H, 0, 512,
                 OFF_PXW2, H, 0, p.pxb2, g_phi, H, 1);
    }
    gsync(&gen, false);
    // e1pre (px@ew1_top + eb1) and gxpre (px@gwih_top + gbih)
    for (int idx = blk; idx < 6400; idx += NBLK) {
        if (idx < 1600) {
            int tm = idx >> 2, tn = idx & 3;
            gemmT<2>(smc, tm * 128, tn * 128, PLAIN(g_phi), H, 0, 512,
                     OFF_EW1, 1024, 0, p.eb1, g_e1pre, H, 0);
        } else {
            int i = idx - 1600;
            int tm = i / 12, tn = i % 12;
            gemmT<2>(smc, tm * 128, tn * 128, PLAIN(g_phi), H, 0, 512,
                     OFF_GWIH, 1024, 0, p.gbih, g_gxpre, G3, 0);
        }
    }
    gsync(&gen, false);

    for (int t = 0; t < T_STEPS; t++) {
        const float* e1pre_t = g_e1pre + (size_t)t * B * H;
        float (*d1h)[B * H] = g_d1hP[t & 1];
        float (*d1hprev)[B * H] = g_d1hP[(t + 1) & 1];

        // ---- P1: pr(0-15) gh(16-63) e1h(64-79) d1h(80-95) d2prev(96-111) ----
        {
            int idx = blk;
            if (idx < 16) {
                int tile = idx >> 1, s = idx & 1;
                gemmT<2>(smc, (tile >> 2) * 128, (tile & 3) * 128, PLAIN(g_h), H, s * 256, 256,
                         OFF_PRW, H, s * 256, s ? 0 : p.prb, g_prP[s], H, 0);
            } else if (idx < 64) {
                int i = idx - 16; int tile = i >> 1, s = i & 1;
                gemmT<2>(smc, (tile / 12) * 128, (tile % 12) * 128, PLAIN(g_h), H, s * 256, 256,
                         OFF_GWHH, H, s * 256, s ? 0 : p.gbhh, g_ghP[s], G3, 0);
            } else if (idx < 80) {
                int i = idx - 64; int tile = i >> 1, s = i & 1;
                gemmT<2>(smc, (tile >> 2) * 128, (tile & 3) * 128, PLAIN(g_h), H, s * 256, 256,
                         OFF_EW1, 1024, 512 + s * 256, 0, g_e1hP[s], H, 0);
            } else if (idx < 96) {
                int i = idx - 80; int tile = i >> 1, s = i & 1;
                gemmT<2>(smc, (tile >> 2) * 128, (tile & 3) * 128, PLAIN(g_h), H, s * 256, 256,
                         OFF_DW1, 1024, 512 + s * 256, s ? 0 : p.db1, d1h[s], H, 0);
            } else if (idx < 112 && t > 0) {
                int i = idx - 96; int tile = i >> 1, s = i & 1;
                ASrc a = {d1hprev[0], d1hprev[1], g_d1pzP[0], g_d1pzP[1], 0, 3};
                gemmT<2>(smc, (tile >> 2) * 128, (tile & 3) * 128, a, H, s * 256, 256,
                         OFF_DW2, H, s * 256, s ? 0 : p.db2, g_d2P[s], H, 0);
            }
            gsync(&gen, false);
        }
        // ---- P2: e2(0-15) pm(16-19) ps(20-23) logits_prev(24-31) ----
        {
            int idx = blk;
            if (idx < 16) {
                int tile = idx >> 1, s = idx & 1;
                ASrc a = {e1pre_t, g_e1hP[0], g_e1hP[1], 0, 0, 2};
                gemmT<2>(smc, (tile >> 2) * 128, (tile & 3) * 128, a, H, s * 256, 256,
                         OFF_EW2, H, s * 256, s ? 0 : p.eb2, g_e2P[s], H, 0);
            } else if (idx < 20) {
                int i = idx - 16; int tile = i >> 1, s = i & 1;
                ASrc a = {g_prP[0], g_prP[1], 0, 0, 0, 1};
                gemmT<1>(smc, tile * 128, 0, a, H, s * 256, 256,
                         OFF_PMW, H, s * 256, s ? 0 : p.pmb, g_pmP[s], ZD, 0);
            } else if (idx < 24) {
                int i = idx - 20; int tile = i >> 1, s = i & 1;
                ASrc a = {g_prP[0], g_prP[1], 0, 0, 0, 1};
                gemmT<1>(smc, tile * 128, 0, a, H, s * 256, 256,
                         OFF_PSW, H, s * 256, s ? 0 : p.psb, g_psP[s], ZD, 0);
            } else if (idx < 32 && t > 0) {
                int i = idx - 24; int tile = i >> 1, s = i & 1;
                ASrc a = {g_d2P[0], g_d2P[1], 0, 0, 0, 1};
                gemmT<2>(smc, (tile >> 1) * 128, (tile & 1) * 128, a, H, s * 256, 256,
                         OFF_DLW, H, s * 256, s ? 0 : p.dlb, g_loP[s], OD, 0);
            }
            gsync(&gen, false);
        }
        // ---- P3: em(0-3) es(4-7) logit-finalize(8-11) ----
        {
            int idx = blk;
            if (idx < 4) {
                int tile = idx >> 1, s = idx & 1;
                ASrc a = {g_e2P[0], g_e2P[1], 0, 0, 0, 1};
                gemmT<1>(smc, tile * 128, 0, a, H, s * 256, 256,
                         OFF_EMW, H, s * 256, s ? 0 : p.emb, g_emP[s], ZD, 0);
            } else if (idx < 8) {
                int i = idx - 4; int tile = i >> 1, s = i & 1;
                ASrc a = {g_e2P[0], g_e2P[1], 0, 0, 0, 1};
                gemmT<1>(smc, tile * 128, 0, a, H, s * 256, 256,
                         OFF_ESW, H, s * 256, s ? 0 : p.esb, g_esP[s], ZD, 0);
            } else if (idx < 12 && t > 0) {
                float* lo = p.olog + (size_t)(t - 1) * B * OD;
                int base = (idx - 8) * 16384;
                for (int e = base + tid; e < base + 16384; e += NTHR)
                    lo[e] = g_loP[0][e] + g_loP[1][e];
            }
            gsync(&gen, false);
        }
        // ---- P4: pz(0-7, K=64) writers(8-11) ----
        {
            const float* eps_t = p.eps + (size_t)t * B * ZD;
            int idx = blk;
            if (idx < 8) {
                ASrc a = {eps_t, g_esP[0], g_esP[1], g_emP[0], g_emP[1], 5};
                gemmT<2>(smc, (idx >> 2) * 128, (idx & 3) * 128, a, ZD, 0, 64,
                         OFF_PZW, ZD, 0, p.pzb, g_pz, H, 1);
            } else if (idx < 12) {
                float* z_t  = p.oz  + (size_t)t * B * ZD;
                float* em_t = p.oem + (size_t)t * B * ZD;
                float* es_t = p.oes + (size_t)t * B * ZD;
                float* pm_t = p.opm + (size_t)t * B * ZD;
                float* ps_t = p.ops + (size_t)t * B * ZD;
                float* kl_t = p.okld + (size_t)t * B * ZD;
                int base = (idx - 8) * 4096;
                for (int e = base + tid; e < base + 4096; e += NTHR) {
                    float em = g_emP[0][e] + g_emP[1][e];
                    float es = spf(g_esP[0][e] + g_esP[1][e]);
                    float pm = g_pmP[0][e] + g_pmP[1][e];
                    float ps = spf(g_psP[0][e] + g_psP[1][e]);
                    em_t[e] = em; es_t[e] = es; pm_t[e] = pm; ps_t[e] = ps;
                    z_t[e] = eps_t[e] * es + em;
                    float d = em - pm;
                    kl_t[e] = 0.5f * (2.f * logf(ps) - 2.f * logf(es)
                                      + (es * es + d * d) / (ps * ps) - 1.f);
                }
            }
            gsync(&gen, false);
        }
        // ---- P5: gx_pz(0-47) d1pz(48-63) ----
        {
            int idx = blk;
            if (idx < 48) {
                int tile = idx >> 1, s = idx & 1;
                gemmT<2>(smc, (tile / 12) * 128, (tile % 12) * 128, PLAIN(g_pz), H, s * 256, 256,
                         OFF_GWIH, 1024, 512 + s * 256, 0, g_gxP[s], G3, 0);
            } else if (idx < 64) {
                int i = idx - 48; int tile = i >> 1, s = i & 1;
                gemmT<2>(smc, (tile >> 2) * 128, (tile & 3) * 128, PLAIN(g_pz), H, s * 256, 256,
                         OFF_DW1, 1024, s * 256, 0, g_d1pzP[s], H, 0);
            }
            gsync(&gen, false);
        }
        // ---- P6: GRU (0-15) ----
        {
            int idx = blk;
            if (idx < 16) {
                const float* gp = g_gxpre + (size_t)t * B * G3;
                int base = idx * 8192;
                for (int e = base + tid; e < base + 8192; e += NTHR) {
                    int b = e >> 9, j = e & 511;
                    size_t o = (size_t)b * G3 + j;
                    float xr = gp[o] + g_gxP[0][o] + g_gxP[1][o];
                    float xz = gp[o + 512] + g_gxP[0][o + 512] + g_gxP[1][o + 512];
                    float xn = gp[o + 1024] + g_gxP[0][o + 1024] + g_gxP[1][o + 1024];
                    float hr = g_ghP[0][o] + g_ghP[1][o];
                    float hz = g_ghP[0][o + 512] + g_ghP[1][o + 512];
                    float hn = g_ghP[0][o + 1024] + g_ghP[1][o + 1024];
                    float rg = 1.f / (1.f + expf(-(xr + hr)));
                    float ug = 1.f / (1.f + expf(-(xz + hz)));
                    float ng = tanhf(xn + rg * hn);
                    g_h[e] = (1.f - ug) * ng + ug * g_h[e];
                }
            }
            gsync(&gen, false);
        }
    }
    // ---- tail: d2(199) final -> g_d2P[0]; logits(199) ----
    {
        int idx = blk;
        if (idx < 8) {
            ASrc a = {g_d1hP[(T_STEPS - 1) & 1][0], g_d1hP[(T_STEPS - 1) & 1][1],
                      g_d1pzP[0], g_d1pzP[1], 0, 3};
            gemmT<2>(smc, (idx >> 2) * 128, (idx & 3) * 128, a, H, 0, 512,
                     OFF_DW2, H, 0, p.db2, g_d2P[0], H, 1);
        }
        gsync(&gen, false);
        if (idx < 4) {
            gemmT<2>(smc, (idx >> 1) * 128, (idx & 1) * 128, PLAIN(g_d2P[0]), H, 0, 512,
                     OFF_DLW, H, 0, p.dlb, p.olog + (size_t)(T_STEPS - 1) * B * OD, OD, 0);
        }
    }
    gsync(&gen, true);
}

extern "C" void kernel_launch(void* const* d_in, const int* in_sizes, int n_in,
                              void* d_out, int out_size) {
    Params p;
    p.x    = (const float*)d_in[0];
    p.eps  = (const float*)d_in[1];
    p.pxw1 = (const float*)d_in[2];  p.pxb1 = (const float*)d_in[3];
    p.pxw2 = (const float*)d_in[4];  p.pxb2 = (const float*)d_in[5];
    p.pzw  = (const float*)d_in[6];  p.pzb  = (const float*)d_in[7];
    p.ew1  = (const float*)d_in[8];  p.eb1  = (const float*)d_in[9];
    p.ew2  = (const float*)d_in[10]; p.eb2  = (const float*)d_in[11];
    p.emw  = (const float*)d_in[12]; p.emb  = (const float*)d_in[13];
    p.esw  = (const float*)d_in[14]; p.esb  = (const float*)d_in[15];
    p.prw  = (const float*)d_in[16]; p.prb  = (const float*)d_in[17];
    p.pmw  = (const float*)d_in[18]; p.pmb  = (const float*)d_in[19];
    p.psw  = (const float*)d_in[20]; p.psb  = (const float*)d_in[21];
    p.dw1  = (const float*)d_in[22]; p.db1  = (const float*)d_in[23];
    p.dw2  = (const float*)d_in[24]; p.db2  = (const float*)d_in[25];
    p.dlw  = (const float*)d_in[26]; p.dlb  = (const float*)d_in[27];
    if (in_sizes[29] == 3 * H) {
        p.gwih = (const float*)d_in[28]; p.gbih = (const float*)d_in[29];
        p.gwhh = (const float*)d_in[30]; p.gbhh = (const float*)d_in[31];
    } else {
        p.gwih = (const float*)d_in[28]; p.gwhh = (const float*)d_in[29];
        p.gbih = (const float*)d_in[30]; p.gbhh = (const float*)d_in[31];
    }

    float* o = (float*)d_out;
    size_t TBZ = (size_t)T_STEPS * B * ZD;
    size_t TBO = (size_t)T_STEPS * B * OD;
    p.oz   = o;
    p.olog = o + TBZ;
    p.oem  = p.olog + TBO;
    p.oes  = p.oem + TBZ;
    p.opm  = p.oes + TBZ;
    p.ops  = p.opm + TBZ;
    p.okld = p.ops + TBZ;

    static bool attr_set = false;
    if (!attr_set) {
        cudaFuncSetAttribute(vrnn_kernel, cudaFuncAttributeMaxDynamicSharedMemorySize, SMEM_BYTES);
        attr_set = true;
    }
    vrnn_kernel<<<NBLK, NTHR, SMEM_BYTES>>>(p);
}

// round 10
// speedup vs baseline: 3.0018x; 1.3227x over previous
#include <cuda_runtime.h>
#include <cuda_bf16.h>
#include <math.h>
#include <stdint.h>

#define T_STEPS 200
#define B 256
#define XD 128
#define H 512
#define ZD 64
#define OD 256
#define G3 1536
#define NBLK 148
#define NTHR 512

// smem (halfword units): per buffer Ah|Al|Wh|Wl, each 128 rows x 72 stride
#define AST 72
#define A_L 9216
#define W_H 18432
#define W_L 27648
#define BUF_H 36864
#define SM_TILES 1024
#define SMEM_BYTES (SM_TILES + 2 * BUF_H * 2)

// transposed bf16 weight offsets ([N][K] layout, element counts)
#define OFF_PXW1 0
#define OFF_PXW2 65536
#define OFF_PZW  327680
#define OFF_EW1  360448
#define OFF_EW2  884736
#define OFF_EMW  1146880
#define OFF_ESW  1179648
#define OFF_PRW  1212416
#define OFF_PMW  1474560
#define OFF_PSW  1507328
#define OFF_DW1  1540096
#define OFF_DW2  2064384
#define OFF_DLW  2326528
#define OFF_GWIH 2457600
#define OFF_GWHH 4030464
#define W_TOTAL  4816896

#define BH (B * H)
#define BZ (B * ZD)
#define BO (B * OD)
#define BG (B * G3)

// ---------------- scratch ----------------
__device__ float g_phi[(size_t)T_STEPS * BH];
__device__ float g_e1pre[(size_t)T_STEPS * BH];
__device__ float g_gxpre[(size_t)T_STEPS * BG];   // px@gwih_top + gbih, all t
__device__ float g_h [BH];
__device__ float g_pz[BH];
__device__ float g_e1hP[4][BH];
__device__ float g_prP [4][BH];
__device__ float g_e2P [4][BH];
__device__ float g_d1P [2][8][BH];   // [t&1][plane]: 0-3 d1h, 4-7 d1pz
__device__ float g_d2P [4][BH];
__device__ float g_emP [4][BZ];
__device__ float g_esP [4][BZ];
__device__ float g_pmP [4][BZ];
__device__ float g_psP [4][BZ];
__device__ float g_loP [4][BO];
__device__ float g_ghP [4][BG];
__device__ float g_gxP [4][BG];
__device__ __align__(16) __nv_bfloat16 g_whi[W_TOTAL];
__device__ __align__(16) __nv_bfloat16 g_wlo[W_TOTAL];

// ---------------- grid barrier ----------------
__device__ unsigned int g_bar = 0;
__device__ volatile unsigned int g_sense = 0;

__device__ __forceinline__ void gsync(unsigned* gen, bool last) {
    __syncthreads();
    if (threadIdx.x == 0) {
        __threadfence();
        unsigned g = *gen;
        if (atomicAdd(&g_bar, 1u) == (unsigned)(NBLK - 1)) {
            g_bar = 0u;
            __threadfence();
            g_sense = last ? 0u : (g + 1u);
        } else {
            while (g_sense == g) { __nanosleep(16); }
            __threadfence();
        }
    }
    __syncthreads();
    (*gen)++;
}

// ---------------- helpers ----------------
__device__ __forceinline__ uint32_t smem_u32(const void* p) {
    uint32_t a;
    asm("{ .reg .u64 t; cvta.to.shared.u64 t, %1; cvt.u32.u64 %0, t; }" : "=r"(a) : "l"(p));
    return a;
}
__device__ __forceinline__ void ldsm4(uint32_t* r, uint32_t addr) {
    asm volatile("ldmatrix.sync.aligned.m8n8.x4.shared.b16 {%0,%1,%2,%3}, [%4];"
                 : "=r"(r[0]), "=r"(r[1]), "=r"(r[2]), "=r"(r[3]) : "r"(addr));
}
__device__ __forceinline__ void mma16816(float* d, const uint32_t* a, const uint32_t* b) {
    asm volatile(
        "mma.sync.aligned.m16n8k16.row.col.f32.bf16.bf16.f32 "
        "{%0,%1,%2,%3}, {%4,%5,%6,%7}, {%8,%9}, {%0,%1,%2,%3};"
        : "+f"(d[0]), "+f"(d[1]), "+f"(d[2]), "+f"(d[3])
        : "r"(a[0]), "r"(a[1]), "r"(a[2]), "r"(a[3]), "r"(b[0]), "r"(b[1]));
}
__device__ __forceinline__ float actf(float v, int act) {
    if (act == 1) return fmaxf(v, 0.f);
    return v;
}
__device__ __forceinline__ float spf(float v) {
    return fmaxf(v, 0.f) + log1pf(expf(-fabsf(v)));
}
__device__ __forceinline__ uint32_t bpack(float a, float b) {
    __nv_bfloat162 h = __floats2bfloat162_rn(a, b);
    return *(uint32_t*)&h;
}

// A-source: mode 0 plain p0; mode 1 relu((p0?)+ Σ_{s<n} pa[s*ps+.]);
// mode 2: p0(eps) * sp(Σ pa) + Σ pb
struct ASrc {
    const float *p0, *pa, *pb;
    int n, ps, mode;
};
__device__ __forceinline__ void ld8(const float* p, size_t o, float* v) {
    float4 a = *(const float4*)(p + o);
    float4 b = *(const float4*)(p + o + 4);
    v[0] = a.x; v[1] = a.y; v[2] = a.z; v[3] = a.w;
    v[4] = b.x; v[5] = b.y; v[6] = b.z; v[7] = b.w;
}
__device__ __forceinline__ void fetch8(float* v, const ASrc& a, size_t o) {
    if (a.mode == 0) { ld8(a.p0, o, v); return; }
    if (a.mode == 1) {
        if (a.p0) ld8(a.p0, o, v);
        else {
#pragma unroll
            for (int i = 0; i < 8; i++) v[i] = 0.f;
        }
        for (int s = 0; s < a.n; s++) {
            float w[8];
            ld8(a.pa + (size_t)s * a.ps, o, w);
#pragma unroll
            for (int i = 0; i < 8; i++) v[i] += w[i];
        }
#pragma unroll
        for (int i = 0; i < 8; i++) v[i] = fmaxf(v[i], 0.f);
        return;
    }
    // mode 2: z = eps * sp(Σ es) + Σ em
    float w[8], u[8];
#pragma unroll
    for (int i = 0; i < 8; i++) { w[i] = 0.f; u[i] = 0.f; }
    ld8(a.p0, o, v);
    for (int s = 0; s < a.n; s++) {
        float x[8];
        ld8(a.pa + (size_t)s * a.ps, o, x);
#pragma unroll
        for (int i = 0; i < 8; i++) w[i] += x[i];
        ld8(a.pb + (size_t)s * a.ps, o, x);
#pragma unroll
        for (int i = 0; i < 8; i++) u[i] += x[i];
    }
#pragma unroll
    for (int i = 0; i < 8; i++) v[i] = v[i] * spf(w[i]) + u[i];
}

// ---------------- mma.sync 128 x (WN*64) GEMM tile, 16 warps ----------------
template<int WN>
__device__ __noinline__ void gemmT(
    char* smc, int row0, int col0,
    ASrc a, int k0, int akbase, int klen,
    int woff, int ldw, int wkbase,
    const float* __restrict__ bias,
    float* __restrict__ C, int ldc, int act)
{
    const int tid = threadIdx.x;
    const int lane = tid & 31, wid = tid >> 5;
    const int wm = wid & 3, wn = wid >> 2;
    const int NC = klen >> 6;
    const uint32_t smb = smem_u32(smc) + SM_TILES;

    float acc[2][2 * WN][4];
#pragma unroll
    for (int i = 0; i < 2; i++)
#pragma unroll
        for (int j = 0; j < 2 * WN; j++)
#pragma unroll
            for (int q = 0; q < 4; q++) acc[i][j][q] = 0.f;

    auto stage = [&](int b, int kb) {
        uint16_t* bb = (uint16_t*)(smc + SM_TILES) + b * BUF_H;
#pragma unroll 2
        for (int it = tid; it < 1024; it += NTHR) {
            int r = it >> 3, kg = (it & 7) << 3;
            size_t o = (size_t)(row0 + r) * k0 + akbase + kb + kg;
            float v[8];
            fetch8(v, a, o);
            uint32_t hw[4], lw[4];
#pragma unroll
            for (int j = 0; j < 4; j++) {
                float h0 = __bfloat162float(__float2bfloat16(v[2 * j]));
                float h1 = __bfloat162float(__float2bfloat16(v[2 * j + 1]));
                hw[j] = bpack(v[2 * j], v[2 * j + 1]);
                lw[j] = bpack(v[2 * j] - h0, v[2 * j + 1] - h1);
            }
            *(uint4*)(bb + r * AST + kg) = make_uint4(hw[0], hw[1], hw[2], hw[3]);
            *(uint4*)(bb + A_L + r * AST + kg) = make_uint4(lw[0], lw[1], lw[2], lw[3]);
        }
#pragma unroll 2
        for (int it = tid; it < WN * 512; it += NTHR) {
            int r = it >> 3, kg = (it & 7) << 3;
            size_t o = (size_t)woff + (size_t)(col0 + r) * ldw + wkbase + kb + kg;
            *(uint4*)(bb + W_H + r * AST + kg) = *(const uint4*)(g_whi + o);
            *(uint4*)(bb + W_L + r * AST + kg) = *(const uint4*)(g_wlo + o);
        }
    };

    const int arow = wm * 32 + (lane & 15);
    const int acolh = (lane >> 4) << 3;
    const int brow = ((lane >> 4) << 3) + (lane & 7);
    const int bko = ((lane >> 3) & 1) << 3;

    stage(0, 0);
    __syncthreads();

    for (int c = 0; c < NC; c++) {
        if (c + 1 < NC) stage((c + 1) & 1, (c + 1) << 6);
        uint32_t bufb = smb + (uint32_t)(c & 1) * (BUF_H * 2);
#pragma unroll
        for (int ks = 0; ks < 4; ks++) {
            uint32_t ah[2][4], al[2][4];
#pragma unroll
            for (int mt = 0; mt < 2; mt++) {
                uint32_t ad = bufb + (uint32_t)(((arow + mt * 16) * AST + (ks << 4) + acolh) << 1);
                ldsm4(ah[mt], ad);
                ldsm4(al[mt], ad + (A_L << 1));
            }
#pragma unroll
            for (int ntp = 0; ntp < WN; ntp++) {
                uint32_t bd = bufb + (uint32_t)((W_H + (wn * (WN * 16) + ntp * 16 + brow) * AST
                                                 + (ks << 4) + bko) << 1);
                uint32_t bh[4], bl[4];
                ldsm4(bh, bd);
                ldsm4(bl, bd + ((W_L - W_H) << 1));
#pragma unroll
                for (int mt = 0; mt < 2; mt++) {
                    mma16816(acc[mt][2 * ntp],     ah[mt], bh);
                    mma16816(acc[mt][2 * ntp],     ah[mt], bl);
                    mma16816(acc[mt][2 * ntp],     al[mt], bh);
                    mma16816(acc[mt][2 * ntp + 1], ah[mt], bh + 2);
                    mma16816(acc[mt][2 * ntp + 1], ah[mt], bl + 2);
                    mma16816(acc[mt][2 * ntp + 1], al[mt], bh + 2);
                }
            }
        }
        __syncthreads();
    }

#pragma unroll
    for (int mt = 0; mt < 2; mt++) {
        int r1 = row0 + wm * 32 + mt * 16 + (lane >> 2);
#pragma unroll
        for (int nt = 0; nt < 2 * WN; nt++) {
            int cc = col0 + wn * (WN * 16) + nt * 8 + ((lane & 3) << 1);
            float bx = 0.f, by = 0.f;
            if (bias) { float2 bv = *(const float2*)(bias + cc); bx = bv.x; by = bv.y; }
            float o0 = actf(acc[mt][nt][0] + bx, act), o1 = actf(acc[mt][nt][1] + by, act);
            float o2 = actf(acc[mt][nt][2] + bx, act), o3 = actf(acc[mt][nt][3] + by, act);
            *(float2*)(C + (size_t)r1 * ldc + cc) = make_float2(o0, o1);
            *(float2*)(C + (size_t)(r1 + 8) * ldc + cc) = make_float2(o2, o3);
        }
    }
}

// ---------------- params ----------------
struct Params {
    const float *x, *eps;
    const float *pxw1, *pxb1, *pxw2, *pxb2;
    const float *pzw, *pzb;
    const float *ew1, *eb1, *ew2, *eb2, *emw, *emb, *esw, *esb;
    const float *prw, *prb, *pmw, *pmb, *psw, *psb;
    const float *dw1, *db1, *dw2, *db2, *dlw, *dlb;
    const float *gwih, *gbih, *gwhh, *gbhh;
    float *oz, *olog, *oem, *oes, *opm, *ops, *okld;
};

__global__ void __launch_bounds__(NTHR, 1) vrnn_kernel(Params p) {
    extern __shared__ char smc[];
    unsigned gen = 0;
    const int tid = threadIdx.x;
    const int blk = blockIdx.x;

    for (int e = blk * NTHR + tid; e < BH; e += NBLK * NTHR) g_h[e] = 0.f;

#define PLAIN(ptr) ASrc{ptr, 0, 0, 0, 0, 0}

    // ---- weight transpose + bf16 hi/lo split ----
    {
        const float* wsrc[15] = {p.pxw1, p.pxw2, p.pzw, p.ew1, p.ew2, p.emw, p.esw, p.prw,
                                 p.pmw, p.psw, p.dw1, p.dw2, p.dlw, p.gwih, p.gwhh};
        const int wk[15] = {128, 512, 64, 1024, 512, 512, 512, 512, 512, 512, 1024, 512, 512, 1024, 512};
        const int wn[15] = {512, 512, 512, 512, 512, 64, 64, 512, 64, 64, 512, 512, 256, 1536, 1536};
        const int wof[15] = {OFF_PXW1, OFF_PXW2, OFF_PZW, OFF_EW1, OFF_EW2, OFF_EMW, OFF_ESW, OFF_PRW,
                             OFF_PMW, OFF_PSW, OFF_DW1, OFF_DW2, OFF_DLW, OFF_GWIH, OFF_GWHH};
        float* tile = (float*)(smc + SM_TILES);
        for (int task = blk; task < 1176; task += NBLK) {
            int tt = task, w = 0;
            for (; w < 15; w++) {
                int nt = (wk[w] >> 6) * (wn[w] >> 6);
                if (tt < nt) break;
                tt -= nt;
            }
            int tkc = wk[w] >> 6;
            int k0 = (tt % tkc) * 64, n0 = (tt / tkc) * 64;
            const float* src = wsrc[w];
            int K = wk[w], N = wn[w];
            for (int it = tid; it < 4096; it += NTHR) {
                int i = it >> 6, j = it & 63;
                tile[i * 68 + j] = src[(size_t)(k0 + i) * N + n0 + j];
            }
            __syncthreads();
            for (int it = tid; it < 4096; it += NTHR) {
                int j = it >> 6, i = it & 63;
                float v = tile[i * 68 + j];
                __nv_bfloat16 hi = __float2bfloat16(v);
                size_t o = (size_t)wof[w] + (size_t)(n0 + j) * K + k0 + i;
                g_whi[o] = hi;
                g_wlo[o] = __float2bfloat16(v - __bfloat162float(hi));
            }
            __syncthreads();
        }
    }
    gsync(&gen, false);

    // ---- preamble ----
    for (int idx = blk; idx < 1600; idx += NBLK) {
        int tm = idx >> 2, tn = idx & 3;
        gemmT<2>(smc, tm * 128, tn * 128, PLAIN(p.x), XD, 0, 128,
                 OFF_PXW1, XD, 0, p.pxb1, g_e1pre, H, 1);
    }
    gsync(&gen, false);
    for (int idx = blk; idx < 1600; idx += NBLK) {
        int tm = idx >> 2, tn = idx & 3;
        gemmT<2>(smc, tm * 128, tn * 128, PLAIN(g_e1pre), H, 0, 512,
                 OFF_PXW2, H, 0, p.pxb2, g_phi, H, 1);
    }
    gsync(&gen, false);
    for (int idx = blk; idx < 6400; idx += NBLK) {
        if (idx < 1600) {
            int tm = idx >> 2, tn = idx & 3;
            gemmT<2>(smc, tm * 128, tn * 128, PLAIN(g_phi), H, 0, 512,
                     OFF_EW1, 1024, 0, p.eb1, g_e1pre, H, 0);
        } else {
            int i = idx - 1600;
            int tm = i / 12, tn = i % 12;
            gemmT<2>(smc, tm * 128, tn * 128, PLAIN(g_phi), H, 0, 512,
                     OFF_GWIH, 1024, 0, p.gbih, g_gxpre, G3, 0);
        }
    }
    gsync(&gen, false);

    for (int t = 0; t < T_STEPS; t++) {
        const float* e1pre_t = g_e1pre + (size_t)t * BH;
        float (*d1)[BH] = g_d1P[t & 1];

        // ---- P1: e1h(0-31) gh(32-127) logits(t-1)(128-143) ----
        {
            int idx = blk;
            if (idx < 32) {
                int tile = idx >> 2, s = idx & 3;
                gemmT<2>(smc, (tile >> 2) * 128, (tile & 3) * 128, PLAIN(g_h),
                         H, s * 128, 128, OFF_EW1, 1024, 512 + s * 128,
                         0, g_e1hP[s], H, 0);
            } else if (idx < 128) {
                int i = idx - 32; int tile = i >> 2, s = i & 3;
                gemmT<2>(smc, (tile / 12) * 128, (tile % 12) * 128, PLAIN(g_h),
                         H, s * 128, 128, OFF_GWHH, H, s * 128,
                         s == 0 ? p.gbhh : 0, g_ghP[s], G3, 0);
            } else if (idx < 144 && t > 0) {
                int i = idx - 128; int tile = i >> 2, s = i & 3;
                ASrc a = {0, g_d2P[0], 0, 4, BH, 1};
                gemmT<2>(smc, (tile >> 1) * 128, (tile & 1) * 128, a,
                         H, s * 128, 128, OFF_DLW, H, s * 128,
                         s == 0 ? p.dlb : 0, g_loP[s], OD, 0);
            }
            gsync(&gen, false);
        }
        // ---- P2: e2(0-31) pr(32-63) d1h(64-95) lofin(96-99) ----
        {
            int idx = blk;
            if (idx < 32) {
                int tile = idx >> 2, s = idx & 3;
                ASrc a = {e1pre_t, g_e1hP[0], 0, 4, BH, 1};
                gemmT<2>(smc, (tile >> 2) * 128, (tile & 3) * 128, a,
                         H, s * 128, 128, OFF_EW2, H, s * 128,
                         s == 0 ? p.eb2 : 0, g_e2P[s], H, 0);
            } else if (idx < 64) {
                int i = idx - 32; int tile = i >> 2, s = i & 3;
                gemmT<2>(smc, (tile >> 2) * 128, (tile & 3) * 128, PLAIN(g_h),
                         H, s * 128, 128, OFF_PRW, H, s * 128,
                         s == 0 ? p.prb : 0, g_prP[s], H, 0);
            } else if (idx < 96) {
                int i = idx - 64; int tile = i >> 2, s = i & 3;
                gemmT<2>(smc, (tile >> 2) * 128, (tile & 3) * 128, PLAIN(g_h),
                         H, s * 128, 128, OFF_DW1, 1024, 512 + s * 128,
                         s == 0 ? p.db1 : 0, d1[s], H, 0);
            } else if (idx < 100 && t > 0) {
                float* lo = p.olog + (size_t)(t - 1) * BO;
                int base = (idx - 96) * 16384;
                for (int e = base + tid; e < base + 16384; e += NTHR)
                    lo[e] = g_loP[0][e] + g_loP[1][e] + g_loP[2][e] + g_loP[3][e];
            }
            gsync(&gen, false);
        }
        // ---- P3: em(0-7) es(8-15) pm(16-23) ps(24-31) ----
        {
            int idx = blk;
            if (idx < 32) {
                int grp = idx >> 3, i = idx & 7;
                int tile = i >> 2, s = i & 3;
                ASrc a = {0, (grp < 2) ? g_e2P[0] : g_prP[0], 0, 4, BH, 1};
                int woff = (grp == 0) ? OFF_EMW : (grp == 1) ? OFF_ESW
                         : (grp == 2) ? OFF_PMW : OFF_PSW;
                const float* bb = (s != 0) ? 0 :
                    ((grp == 0) ? p.emb : (grp == 1) ? p.esb : (grp == 2) ? p.pmb : p.psb);
                float* out = (grp == 0) ? g_emP[s] : (grp == 1) ? g_esP[s]
                           : (grp == 2) ? g_pmP[s] : g_psP[s];
                gemmT<1>(smc, tile * 128, 0, a, H, s * 128, 128,
                         woff, H, s * 128, bb, out, ZD, 0);
            }
            gsync(&gen, false);
        }
        // ---- P4: pz(0-7, K=64) writers(8-11) ----
        {
            const float* eps_t = p.eps + (size_t)t * BZ;
            int idx = blk;
            if (idx < 8) {
                ASrc a = {eps_t, g_esP[0], g_emP[0], 4, BZ, 2};
                gemmT<2>(smc, (idx >> 2) * 128, (idx & 3) * 128, a, ZD, 0, 64,
                         OFF_PZW, ZD, 0, p.pzb, g_pz, H, 1);
            } else if (idx < 12) {
                float* z_t  = p.oz  + (size_t)t * BZ;
                float* em_t = p.oem + (size_t)t * BZ;
                float* es_t = p.oes + (size_t)t * BZ;
                float* pm_t = p.opm + (size_t)t * BZ;
                float* ps_t = p.ops + (size_t)t * BZ;
                float* kl_t = p.okld + (size_t)t * BZ;
                int base = (idx - 8) * 4096;
                for (int e = base + tid; e < base + 4096; e += NTHR) {
                    float em = g_emP[0][e] + g_emP[1][e] + g_emP[2][e] + g_emP[3][e];
                    float es = spf(g_esP[0][e] + g_esP[1][e] + g_esP[2][e] + g_esP[3][e]);
                    float pm = g_pmP[0][e] + g_pmP[1][e] + g_pmP[2][e] + g_pmP[3][e];
                    float ps = spf(g_psP[0][e] + g_psP[1][e] + g_psP[2][e] + g_psP[3][e]);
                    em_t[e] = em; es_t[e] = es; pm_t[e] = pm; ps_t[e] = ps;
                    z_t[e] = eps_t[e] * es + em;
                    float d = em - pm;
                    kl_t[e] = 0.5f * (2.f * logf(ps) - 2.f * logf(es)
                                      + (es * es + d * d) / (ps * ps) - 1.f);
                }
            }
            gsync(&gen, false);
        }
        // ---- P5: gx_pz(0-95) d1pz(96-127) ----
        {
            int idx = blk;
            if (idx < 96) {
                int tile = idx >> 2, s = idx & 3;
                gemmT<2>(smc, (tile / 12) * 128, (tile % 12) * 128, PLAIN(g_pz),
                         H, s * 128, 128, OFF_GWIH, 1024, 512 + s * 128,
                         0, g_gxP[s], G3, 0);
            } else if (idx < 128) {
                int i = idx - 96; int tile = i >> 2, s = i & 3;
                gemmT<2>(smc, (tile >> 2) * 128, (tile & 3) * 128, PLAIN(g_pz),
                         H, s * 128, 128, OFF_DW1, 1024, s * 128,
                         0, d1[4 + s], H, 0);
            }
            gsync(&gen, false);
        }
        // ---- P6: GRU(0-15) d2(16-47) ----
        {
            int idx = blk;
            if (idx < 16) {
                const float* gp = g_gxpre + (size_t)t * BG;
                int base = idx * 8192;
                for (int e = base + tid; e < base + 8192; e += NTHR) {
                    int b = e >> 9, j = e & 511;
                    size_t o = (size_t)b * G3 + j;
                    float xr = gp[o], xz = gp[o + 512], xn = gp[o + 1024];
                    float hr = 0.f, hz = 0.f, hn = 0.f;
#pragma unroll
                    for (int s = 0; s < 4; s++) {
                        xr += g_gxP[s][o]; xz += g_gxP[s][o + 512]; xn += g_gxP[s][o + 1024];
                        hr += g_ghP[s][o]; hz += g_ghP[s][o + 512]; hn += g_ghP[s][o + 1024];
                    }
                    float rg = 1.f / (1.f + expf(-(xr + hr)));
                    float ug = 1.f / (1.f + expf(-(xz + hz)));
                    float ng = tanhf(xn + rg * hn);
                    g_h[e] = (1.f - ug) * ng + ug * g_h[e];
                }
            } else if (idx < 48) {
                int i = idx - 16; int tile = i >> 2, s = i & 3;
                ASrc a = {0, d1[0], 0, 8, BH, 1};
                gemmT<2>(smc, (tile >> 2) * 128, (tile & 3) * 128, a,
                         H, s * 128, 128, OFF_DW2, H, s * 128,
                         s == 0 ? p.db2 : 0, g_d2P[s], H, 0);
            }
            gsync(&gen, false);
        }
    }
    // ---- tail: logits(199) ----
    {
        int idx = blk;
        if (idx < 16) {
            int tile = idx >> 2, s = idx & 3;
            ASrc a = {0, g_d2P[0], 0, 4, BH, 1};
            gemmT<2>(smc, (tile >> 1) * 128, (tile & 1) * 128, a,
                     H, s * 128, 128, OFF_DLW, H, s * 128,
                     s == 0 ? p.dlb : 0, g_loP[s], OD, 0);
        }
        gsync(&gen, false);
        if (idx < 4) {
            float* lo = p.olog + (size_t)(T_STEPS - 1) * BO;
            int base = idx * 16384;
            for (int e = base + tid; e < base + 16384; e += NTHR)
                lo[e] = g_loP[0][e] + g_loP[1][e] + g_loP[2][e] + g_loP[3][e];
        }
    }
    gsync(&gen, true);
}

extern "C" void kernel_launch(void* const* d_in, const int* in_sizes, int n_in,
                              void* d_out, int out_size) {
    Params p;
    p.x    = (const float*)d_in[0];
    p.eps  = (const float*)d_in[1];
    p.pxw1 = (const float*)d_in[2];  p.pxb1 = (const float*)d_in[3];
    p.pxw2 = (const float*)d_in[4];  p.pxb2 = (const float*)d_in[5];
    p.pzw  = (const float*)d_in[6];  p.pzb  = (const float*)d_in[7];
    p.ew1  = (const float*)d_in[8];  p.eb1  = (const float*)d_in[9];
    p.ew2  = (const float*)d_in[10]; p.eb2  = (const float*)d_in[11];
    p.emw  = (const float*)d_in[12]; p.emb  = (const float*)d_in[13];
    p.esw  = (const float*)d_in[14]; p.esb  = (const float*)d_in[15];
    p.prw  = (const float*)d_in[16]; p.prb  = (const float*)d_in[17];
    p.pmw  = (const float*)d_in[18]; p.pmb  = (const float*)d_in[19];
    p.psw  = (const float*)d_in[20]; p.psb  = (const float*)d_in[21];
    p.dw1  = (const float*)d_in[22]; p.db1  = (const float*)d_in[23];
    p.dw2  = (const float*)d_in[24]; p.db2  = (const float*)d_in[25];
    p.dlw  = (const float*)d_in[26]; p.dlb  = (const float*)d_in[27];
    if (in_sizes[29] == 3 * H) {
        p.gwih = (const float*)d_in[28]; p.gbih = (const float*)d_in[29];
        p.gwhh = (const float*)d_in[30]; p.gbhh = (const float*)d_in[31];
    } else {
        p.gwih = (const float*)d_in[28]; p.gwhh = (const float*)d_in[29];
        p.gbih = (const float*)d_in[30]; p.gbhh = (const float*)d_in[31];
    }

    float* o = (float*)d_out;
    size_t TBZ = (size_t)T_STEPS * B * ZD;
    size_t TBO = (size_t)T_STEPS * B * OD;
    p.oz   = o;
    p.olog = o + TBZ;
    p.oem  = p.olog + TBO;
    p.oes  = p.oem + TBZ;
    p.opm  = p.oes + TBZ;
    p.ops  = p.opm + TBZ;
    p.okld = p.ops + TBZ;

    static bool attr_set = false;
    if (!attr_set) {
        cudaFuncSetAttribute(vrnn_kernel, cudaFuncAttributeMaxDynamicSharedMemorySize, SMEM_BYTES);
        attr_set = true;
    }
    vrnn_kernel<<<NBLK, NTHR, SMEM_BYTES>>>(p);
}